// round 4
// baseline (speedup 1.0000x reference)
#include <cuda_runtime.h>

#define BATCH 64
#define T 128
#define N 32
#define M 8
#define P 16
#define MA 34    // padded row stride (even -> float2-aligned rows)
#define NCH 8    // backward-scan chunks
#define CHS 16   // chunk size (last chunk has 15)

// Global scratch
__device__ float g_muf[BATCH * T * N];
__device__ float g_mup[BATCH * T * N];
__device__ float g_Sigf[(size_t)BATCH * T * N * N];
__device__ float g_Sigp[(size_t)BATCH * T * N * N];
__device__ float g_J[(size_t)BATCH * (T - 1) * N * N];   // X_t = J_t^T
__device__ float g_M[(size_t)BATCH * (T - 1) * N * N];   // M_t
__device__ float g_c[(size_t)BATCH * (T - 1) * N];       // c_t
__device__ float g_OX[(size_t)BATCH * NCH * N * N];      // chunk op X
__device__ float g_OM[(size_t)BATCH * NCH * N * N];      // chunk op M
__device__ float g_Oc[(size_t)BATCH * NCH * N];          // chunk op c
__device__ float g_eS[(size_t)BATCH * NCH * N * N];      // chunk entry Sigma
__device__ float g_emu[(size_t)BATCH * NCH * N];         // chunk entry mu

// =====================================================================
// Kernel 1: forward Kalman filter. One CTA (256 thr) per batch element.
// (unchanged from round 3)
// =====================================================================
__global__ __launch_bounds__(256, 1) void k_fwd(
    const float* __restrict__ Y, const float* __restrict__ U,
    const float* __restrict__ A, const float* __restrict__ Bm,
    const float* __restrict__ C, const float* __restrict__ mu0,
    const float* __restrict__ Sig0)
{
    const int b = blockIdx.x;
    const int tid = threadIdx.x;

    __shared__ __align__(16) float sA[2][N * MA];
    __shared__ __align__(16) float sC[2][P * MA];
    __shared__ __align__(16) float sB[2][N * M];
    __shared__ float sy[2][P], su[2][M];
    __shared__ __align__(16) float sSig[N * MA], sAS[N * MA], sSigp[N * MA];
    __shared__ __align__(16) float sCSp[P * MA];
    __shared__ __align__(16) float sS[P * 18];
    __shared__ __align__(16) float sX[P * MA];     // X = K^T (16 x 32)
    __shared__ float smu[N], smup[N], sd[P];

    if (tid < N) smu[tid] = mu0[tid];
    for (int i2 = tid; i2 < 512; i2 += 256) {
        int r = i2 >> 4, c2 = i2 & 15;
        *(float2*)(sSig + r * MA + 2 * c2) = ((const float2*)Sig0)[i2];
    }
    {
        const size_t bt = (size_t)b * T;
        const float2* Ab = (const float2*)(A + bt * (N * N));
        const float2* Cb = (const float2*)(C + bt * (P * N));
        const float2* Bb = (const float2*)(Bm + bt * (N * M));
        for (int i2 = tid; i2 < 512; i2 += 256) {
            int r = i2 >> 4, c2 = i2 & 15;
            *(float2*)(sA[0] + r * MA + 2 * c2) = Ab[i2];
        }
        for (int i2 = tid; i2 < 256; i2 += 256) {
            int r = i2 >> 4, c2 = i2 & 15;
            *(float2*)(sC[0] + r * MA + 2 * c2) = Cb[i2];
        }
        if (tid < 128) ((float2*)sB[0])[tid] = Bb[tid];
        if (tid < P) sy[0][tid] = Y[bt * P + tid];
        if (tid < M) su[0][tid] = U[bt * M + tid];
    }
    __syncthreads();

    const int tr = tid >> 4, tc = tid & 15;
    const int r0 = tr * 2, c0 = tc * 2;

    for (int t = 0; t < T; t++) {
        const int cur = t & 1, nxt = cur ^ 1;
        const size_t bt = (size_t)b * T + t;
        const float* Ac = sA[cur];
        const float* Cc = sC[cur];

        // ---- R0: mu_p (warp0) + AS = A*Sig ----
        if (tid < N) {
            const float2* Ar = (const float2*)(Ac + tid * MA);
            float s = 0.f;
            #pragma unroll
            for (int j = 0; j < 16; j++) {
                float2 a = Ar[j];
                s += a.x * smu[2 * j] + a.y * smu[2 * j + 1];
            }
            const float2* Br = (const float2*)(sB[cur] + tid * M);
            #pragma unroll
            for (int j = 0; j < 4; j++) {
                float2 bb = Br[j];
                s += bb.x * su[cur][2 * j] + bb.y * su[cur][2 * j + 1];
            }
            smup[tid] = s;
            g_mup[bt * N + tid] = s;
        }
        {
            const float2* Xr0 = (const float2*)(Ac + r0 * MA);
            const float2* Xr1 = (const float2*)(Ac + (r0 + 1) * MA);
            float a00 = 0, a01 = 0, a10 = 0, a11 = 0;
            #pragma unroll
            for (int k2 = 0; k2 < 16; k2++) {
                float2 x0 = Xr0[k2], x1 = Xr1[k2];
                float2 y0 = *(const float2*)(sSig + (2 * k2) * MA + c0);
                float2 y1 = *(const float2*)(sSig + (2 * k2 + 1) * MA + c0);
                a00 += x0.x * y0.x + x0.y * y1.x;  a01 += x0.x * y0.y + x0.y * y1.y;
                a10 += x1.x * y0.x + x1.y * y1.x;  a11 += x1.x * y0.y + x1.y * y1.y;
            }
            *(float2*)(sAS + r0 * MA + c0) = make_float2(a00, a01);
            *(float2*)(sAS + (r0 + 1) * MA + c0) = make_float2(a10, a11);
        }
        __syncthreads();

        // ---- R1: Sig_p = AS * A^T + Q ----
        {
            const float2* Xr0 = (const float2*)(sAS + r0 * MA);
            const float2* Xr1 = (const float2*)(sAS + (r0 + 1) * MA);
            const float2* Yc0 = (const float2*)(Ac + c0 * MA);
            const float2* Yc1 = (const float2*)(Ac + (c0 + 1) * MA);
            float a00 = (r0 == c0) ? 0.01f : 0.f, a01 = 0, a10 = 0;
            float a11 = (r0 == c0) ? 0.01f : 0.f;
            #pragma unroll
            for (int k2 = 0; k2 < 16; k2++) {
                float2 x0 = Xr0[k2], x1 = Xr1[k2], y0 = Yc0[k2], y1 = Yc1[k2];
                a00 += x0.x * y0.x + x0.y * y0.y;  a01 += x0.x * y1.x + x0.y * y1.y;
                a10 += x1.x * y0.x + x1.y * y0.y;  a11 += x1.x * y1.x + x1.y * y1.y;
            }
            *(float2*)(sSigp + r0 * MA + c0) = make_float2(a00, a01);
            *(float2*)(sSigp + (r0 + 1) * MA + c0) = make_float2(a10, a11);
        }
        __syncthreads();

        // ---- R2: CSp = C*Sig_p (tid<128) | resid (128..143) ----
        if (tid < 128) {
            const int rr = (tid >> 4) * 2, cc = (tid & 15) * 2;
            const float2* Xr0 = (const float2*)(Cc + rr * MA);
            const float2* Xr1 = (const float2*)(Cc + (rr + 1) * MA);
            float a00 = 0, a01 = 0, a10 = 0, a11 = 0;
            #pragma unroll
            for (int k2 = 0; k2 < 16; k2++) {
                float2 x0 = Xr0[k2], x1 = Xr1[k2];
                float2 y0 = *(const float2*)(sSigp + (2 * k2) * MA + cc);
                float2 y1 = *(const float2*)(sSigp + (2 * k2 + 1) * MA + cc);
                a00 += x0.x * y0.x + x0.y * y1.x;  a01 += x0.x * y0.y + x0.y * y1.y;
                a10 += x1.x * y0.x + x1.y * y1.x;  a11 += x1.x * y0.y + x1.y * y1.y;
            }
            *(float2*)(sCSp + rr * MA + cc) = make_float2(a00, a01);
            *(float2*)(sCSp + (rr + 1) * MA + cc) = make_float2(a10, a11);
        } else if (tid < 144) {
            const int i = tid - 128;
            const float2* Cr = (const float2*)(Cc + i * MA);
            float s = sy[cur][i];
            #pragma unroll
            for (int j = 0; j < 16; j++) {
                float2 cv = Cr[j];
                s -= cv.x * smup[2 * j] + cv.y * smup[2 * j + 1];
            }
            sd[i] = s;
        }
        __syncthreads();

        // ---- R3: S = CSp*C^T + R (tid<64) | STG Sig_p (tid>=64) ----
        if (tid < 64) {
            const int rr = (tid >> 3) * 2, cc = (tid & 7) * 2;
            const float2* Xr0 = (const float2*)(sCSp + rr * MA);
            const float2* Xr1 = (const float2*)(sCSp + (rr + 1) * MA);
            const float2* Yc0 = (const float2*)(Cc + cc * MA);
            const float2* Yc1 = (const float2*)(Cc + (cc + 1) * MA);
            float a00 = (rr == cc) ? 0.01f : 0.f, a01 = 0, a10 = 0;
            float a11 = (rr == cc) ? 0.01f : 0.f;
            #pragma unroll
            for (int k2 = 0; k2 < 16; k2++) {
                float2 x0 = Xr0[k2], x1 = Xr1[k2], y0 = Yc0[k2], y1 = Yc1[k2];
                a00 += x0.x * y0.x + x0.y * y0.y;  a01 += x0.x * y1.x + x0.y * y1.y;
                a10 += x1.x * y0.x + x1.y * y0.y;  a11 += x1.x * y1.x + x1.y * y1.y;
            }
            *(float2*)(sS + rr * 18 + cc) = make_float2(a00, a01);
            *(float2*)(sS + (rr + 1) * 18 + cc) = make_float2(a10, a11);
        } else {
            float2* gp = (float2*)(g_Sigp + (bt << 10));
            for (int i2 = tid - 64; i2 < 512; i2 += 192) {
                int r = i2 >> 4, c2 = i2 & 15;
                gp[i2] = *(const float2*)(sSigp + r * MA + 2 * c2);
            }
        }
        __syncthreads();

        // ---- R4: warp0 solves S X = CSp; warps 1-7 prefetch t+1 ----
        if (tid < 32) {
            const int c = tid;
            float Sc[P], Rc[P], piv[P];
            #pragma unroll
            for (int r = 0; r < P; r++) {
                Sc[r] = sS[r * 18 + (c & 15)];
                Rc[r] = sCSp[r * MA + c];
            }
            #pragma unroll
            for (int j = 0; j < P; j++) {
                float f[P];
                #pragma unroll
                for (int r = 0; r < P; r++) f[r] = __shfl_sync(0xffffffffu, Sc[r], j);
                float pinv = 1.0f / f[j];
                piv[j] = f[j];
                float sj = Sc[j] * pinv, rj = Rc[j] * pinv;
                #pragma unroll
                for (int r = 0; r < P; r++) {
                    if (r != j) { Sc[r] -= f[r] * sj; Rc[r] -= f[r] * rj; }
                }
            }
            #pragma unroll
            for (int r = 0; r < P; r++) sX[r * MA + c] = Rc[r] / piv[r];
        } else if (t + 1 < T) {
            const int pt = tid - 32;
            const size_t bt1 = bt + 1;
            const float2* An = (const float2*)(A + bt1 * (N * N));
            const float2* Cn = (const float2*)(C + bt1 * (P * N));
            const float2* Bn = (const float2*)(Bm + bt1 * (N * M));
            for (int i2 = pt; i2 < 512; i2 += 224) {
                int r = i2 >> 4, c2 = i2 & 15;
                *(float2*)(sA[nxt] + r * MA + 2 * c2) = An[i2];
            }
            for (int i2 = pt; i2 < 256; i2 += 224) {
                int r = i2 >> 4, c2 = i2 & 15;
                *(float2*)(sC[nxt] + r * MA + 2 * c2) = Cn[i2];
            }
            if (pt < 128) ((float2*)sB[nxt])[pt] = Bn[pt];
            if (pt < P) sy[nxt][pt] = Y[bt1 * P + pt];
            else if (pt < P + M) su[nxt][pt - P] = U[bt1 * M + (pt - P)];
        }
        __syncthreads();

        // ---- R5: mu_f (warp0) + Sf = Sigp - 0.5*(X^T Z + Z^T X), fused sym ----
        if (tid < N) {
            float s = smup[tid];
            #pragma unroll
            for (int j = 0; j < P; j++) s += sX[j * MA + tid] * sd[j];
            smu[tid] = s;
            g_muf[bt * N + tid] = s;
        }
        {
            float2 p0 = *(const float2*)(sSigp + r0 * MA + c0);
            float2 p1 = *(const float2*)(sSigp + (r0 + 1) * MA + c0);
            float m00 = 0, m01 = 0, m10 = 0, m11 = 0;
            #pragma unroll
            for (int j = 0; j < P; j++) {
                float2 xr = *(const float2*)(sX + j * MA + r0);
                float2 xc = *(const float2*)(sX + j * MA + c0);
                float2 zr = *(const float2*)(sCSp + j * MA + r0);
                float2 zc = *(const float2*)(sCSp + j * MA + c0);
                m00 += xr.x * zc.x + zr.x * xc.x;
                m01 += xr.x * zc.y + zr.x * xc.y;
                m10 += xr.y * zc.x + zr.y * xc.x;
                m11 += xr.y * zc.y + zr.y * xc.y;
            }
            float v00 = p0.x - 0.5f * m00, v01 = p0.y - 0.5f * m01;
            float v10 = p1.x - 0.5f * m10, v11 = p1.y - 0.5f * m11;
            *(float2*)(sSig + r0 * MA + c0) = make_float2(v00, v01);
            *(float2*)(sSig + (r0 + 1) * MA + c0) = make_float2(v10, v11);
            float* gf = g_Sigf + (bt << 10);
            *(float2*)(gf + r0 * 32 + c0) = make_float2(v00, v01);
            *(float2*)(gf + (r0 + 1) * 32 + c0) = make_float2(v10, v11);
        }
        __syncthreads();
    }
}

// =====================================================================
// Kernel 2: per (b,t) compute X_t = J_t^T, M_t, c_t. grid (127, 64).
// =====================================================================
#define MAJ 33
__global__ __launch_bounds__(128) void k_J2(const float* __restrict__ A)
{
    const int t = blockIdx.x;      // 0..126
    const int b = blockIdx.y;
    const size_t bt = (size_t)b * T + t;
    const int tid = threadIdx.x;

    __shared__ float sA[N * MAJ], sSf[N * MAJ], sSp[N * MAJ];
    __shared__ float sG[N * MAJ], sG0[N * MAJ];
    __shared__ float sfac[N], spiv[N], smf[N], smp[N];

    const float* Ab = A + bt * (N * N);
    const float* gf = g_Sigf + (bt << 10);
    const float* gp = g_Sigp + ((bt + 1) << 10);
    for (int i = tid; i < N * N; i += 128) {
        int r = i >> 5, c = i & 31;
        sA[r * MAJ + c] = Ab[i];
        sSf[r * MAJ + c] = gf[i];
        sSp[r * MAJ + c] = gp[i];
    }
    if (tid < N) {
        smf[tid] = g_muf[bt * N + tid];
        smp[tid] = g_mup[(bt + 1) * N + tid];
    }
    __syncthreads();

    // G = A * Sf
    #pragma unroll
    for (int s = 0; s < 2; s++) {
        const int id = tid + s * 128;
        const int rr = (id >> 4) * 2, cc = (id & 15) * 2;
        float a00 = 0, a01 = 0, a10 = 0, a11 = 0;
        #pragma unroll
        for (int k = 0; k < N; k++) {
            float x0 = sA[rr * MAJ + k], x1 = sA[(rr + 1) * MAJ + k];
            float y0 = sSf[k * MAJ + cc], y1 = sSf[k * MAJ + cc + 1];
            a00 += x0 * y0; a01 += x0 * y1; a10 += x1 * y0; a11 += x1 * y1;
        }
        sG[rr * MAJ + cc] = a00;        sG0[rr * MAJ + cc] = a00;
        sG[rr * MAJ + cc + 1] = a01;    sG0[rr * MAJ + cc + 1] = a01;
        sG[(rr + 1) * MAJ + cc] = a10;  sG0[(rr + 1) * MAJ + cc] = a10;
        sG[(rr + 1) * MAJ + cc + 1] = a11; sG0[(rr + 1) * MAJ + cc + 1] = a11;
    }
    __syncthreads();

    // Gauss-Jordan on [Sp | G]  ->  X = Sp^{-1} G
    #pragma unroll 1
    for (int j = 0; j < N; j++) {
        if (tid < N) sfac[tid] = sSp[tid * MAJ + j];
        __syncthreads();
        float pinv = 1.0f / sfac[j];
        if (tid == 0) spiv[j] = sfac[j];
        for (int i = tid; i < N * 64; i += 128) {
            int r = i >> 6, c = i & 63;
            float* mat = (c < N) ? sSp : sG;
            int cc = c & 31;
            if (r != j) mat[r * MAJ + cc] -= sfac[r] * pinv * mat[j * MAJ + cc];
        }
        __syncthreads();
    }

    // X -> sA (overwrite) and g_J
    const size_t jidx = (size_t)b * (T - 1) + t;
    float* gj = g_J + jidx * (N * N);
    for (int i = tid; i < N * N; i += 128) {
        int r = i >> 5, c = i & 31;
        float x = sG[r * MAJ + c] / spiv[r];
        sA[r * MAJ + c] = x;
        gj[i] = x;
    }
    __syncthreads();

    // c = mf - X^T mp ; M = Sf - 0.5 (X^T G0 + G0^T X)
    if (tid < N) {
        float s = smf[tid];
        #pragma unroll
        for (int k = 0; k < N; k++) s -= sA[k * MAJ + tid] * smp[k];
        g_c[jidx * N + tid] = s;
    }
    float* gm = g_M + jidx * (N * N);
    for (int i = tid; i < N * N; i += 128) {
        int r = i >> 5, c = i & 31;
        float m = 0.f;
        #pragma unroll
        for (int k = 0; k < N; k++)
            m += sA[k * MAJ + r] * sG0[k * MAJ + c] + sA[k * MAJ + c] * sG0[k * MAJ + r];
        gm[i] = sSf[r * MAJ + c] - 0.5f * m;
    }
}

// =====================================================================
// Kernel 3 (Phase A): compose chunk operators. grid (8, 64), 256 thr.
// =====================================================================
__global__ __launch_bounds__(256) void k_scanA()
{
    const int k = blockIdx.x, b = blockIdx.y;
    const int t_lo = CHS * k;
    const int t_hi = (k == NCH - 1) ? (T - 2) : (CHS * k + CHS - 1);
    const int tid = threadIdx.x;

    __shared__ __align__(16) float sXO[N * MA], sMO[N * MA];
    __shared__ __align__(16) float sXt[N * MA], sMt[N * MA];
    __shared__ __align__(16) float sW[N * MA], sXN[N * MA];
    __shared__ float scO[N], sct[N], scN[N];

    const int r0 = (tid >> 4) * 2, c0 = (tid & 15) * 2;

    // O = E_{t_hi}
    {
        const size_t base = (size_t)b * (T - 1) + t_hi;
        const float2* gx = (const float2*)(g_J + base * (N * N));
        const float2* gm = (const float2*)(g_M + base * (N * N));
        for (int i2 = tid; i2 < 512; i2 += 256) {
            int r = i2 >> 4, c = (i2 & 15) * 2;
            *(float2*)(sXO + r * MA + c) = gx[i2];
            *(float2*)(sMO + r * MA + c) = gm[i2];
        }
        if (tid < N) scO[tid] = g_c[base * N + tid];
    }
    __syncthreads();

    for (int t = t_hi - 1; t >= t_lo; t--) {
        const size_t base = (size_t)b * (T - 1) + t;
        {
            const float2* gx = (const float2*)(g_J + base * (N * N));
            const float2* gm = (const float2*)(g_M + base * (N * N));
            for (int i2 = tid; i2 < 512; i2 += 256) {
                int r = i2 >> 4, c = (i2 & 15) * 2;
                *(float2*)(sXt + r * MA + c) = gx[i2];
                *(float2*)(sMt + r * MA + c) = gm[i2];
            }
            if (tid < N) sct[tid] = g_c[base * N + tid];
        }
        __syncthreads();

        // region1: W = MO*Xt ; XN = XO*Xt ; scN = ct + Xt^T cO (warp0)
        {
            const float2* Mr0 = (const float2*)(sMO + r0 * MA);
            const float2* Mr1 = (const float2*)(sMO + (r0 + 1) * MA);
            const float2* Or0 = (const float2*)(sXO + r0 * MA);
            const float2* Or1 = (const float2*)(sXO + (r0 + 1) * MA);
            float w00 = 0, w01 = 0, w10 = 0, w11 = 0;
            float x00 = 0, x01 = 0, x10 = 0, x11 = 0;
            #pragma unroll
            for (int k2 = 0; k2 < 16; k2++) {
                float2 y0 = *(const float2*)(sXt + (2 * k2) * MA + c0);
                float2 y1 = *(const float2*)(sXt + (2 * k2 + 1) * MA + c0);
                float2 m0 = Mr0[k2], m1 = Mr1[k2];
                float2 o0 = Or0[k2], o1 = Or1[k2];
                w00 += m0.x * y0.x + m0.y * y1.x;  w01 += m0.x * y0.y + m0.y * y1.y;
                w10 += m1.x * y0.x + m1.y * y1.x;  w11 += m1.x * y0.y + m1.y * y1.y;
                x00 += o0.x * y0.x + o0.y * y1.x;  x01 += o0.x * y0.y + o0.y * y1.y;
                x10 += o1.x * y0.x + o1.y * y1.x;  x11 += o1.x * y0.y + o1.y * y1.y;
            }
            *(float2*)(sW + r0 * MA + c0) = make_float2(w00, w01);
            *(float2*)(sW + (r0 + 1) * MA + c0) = make_float2(w10, w11);
            *(float2*)(sXN + r0 * MA + c0) = make_float2(x00, x01);
            *(float2*)(sXN + (r0 + 1) * MA + c0) = make_float2(x10, x11);
        }
        if (tid < N) {
            float s = sct[tid];
            #pragma unroll
            for (int j = 0; j < N; j++) s += sXt[j * MA + tid] * scO[j];
            scN[tid] = s;
        }
        __syncthreads();

        // region2: MO' = Mt + Xt^T W ; XO <- XN ; cO <- cN
        {
            float2 f0 = *(const float2*)(sMt + r0 * MA + c0);
            float2 f1 = *(const float2*)(sMt + (r0 + 1) * MA + c0);
            float a00 = f0.x, a01 = f0.y, a10 = f1.x, a11 = f1.y;
            #pragma unroll
            for (int j = 0; j < N; j++) {
                float2 xj = *(const float2*)(sXt + j * MA + r0);
                float2 wj = *(const float2*)(sW + j * MA + c0);
                a00 += xj.x * wj.x;  a01 += xj.x * wj.y;
                a10 += xj.y * wj.x;  a11 += xj.y * wj.y;
            }
            *(float2*)(sMO + r0 * MA + c0) = make_float2(a00, a01);
            *(float2*)(sMO + (r0 + 1) * MA + c0) = make_float2(a10, a11);
            *(float2*)(sXO + r0 * MA + c0) = *(const float2*)(sXN + r0 * MA + c0);
            *(float2*)(sXO + (r0 + 1) * MA + c0) = *(const float2*)(sXN + (r0 + 1) * MA + c0);
        }
        if (tid < N) scO[tid] = scN[tid];
        __syncthreads();
    }

    // store chunk operator
    {
        const size_t obase = (size_t)b * NCH + k;
        float2* gx = (float2*)(g_OX + obase * (N * N));
        float2* gm = (float2*)(g_OM + obase * (N * N));
        for (int i2 = tid; i2 < 512; i2 += 256) {
            int r = i2 >> 4, c = (i2 & 15) * 2;
            gx[i2] = *(const float2*)(sXO + r * MA + c);
            gm[i2] = *(const float2*)(sMO + r * MA + c);
        }
        if (tid < N) g_Oc[obase * N + tid] = scO[tid];
    }
}

// =====================================================================
// Kernel 4 (Phase B): boundary states per batch. grid 64, 256 thr.
// =====================================================================
__global__ __launch_bounds__(256) void k_scanB(float* __restrict__ out)
{
    const int b = blockIdx.x;
    const int tid = threadIdx.x;

    __shared__ __align__(16) float sS[N * MA], sX[N * MA], sMm[N * MA], sW[N * MA];
    __shared__ float smu[N], smuN[N], sc[N];

    const int r0 = (tid >> 4) * 2, c0 = (tid & 15) * 2;

    // state at t = T-1 (= filtered); write out; store entry[NCH-1]
    {
        const size_t btL = (size_t)b * T + (T - 1);
        const float2* gf = (const float2*)(g_Sigf + (btL << 10));
        float2* ge = (float2*)(g_eS + ((size_t)b * NCH + (NCH - 1)) * (N * N));
        for (int i2 = tid; i2 < 512; i2 += 256) {
            int r = i2 >> 4, c = (i2 & 15) * 2;
            float2 v = gf[i2];
            *(float2*)(sS + r * MA + c) = v;
            ge[i2] = v;
            float* o = out + (btL * N + r) * (N + 1) + 1 + c;
            o[0] = v.x; o[1] = v.y;
        }
        if (tid < N) {
            float v = g_muf[btL * N + tid];
            smu[tid] = v;
            g_emu[((size_t)b * NCH + (NCH - 1)) * N + tid] = v;
            out[(btL * N + tid) * (N + 1)] = v;
        }
    }
    __syncthreads();

    for (int k = NCH - 2; k >= 0; k--) {
        const size_t obase = (size_t)b * NCH + (k + 1);
        {
            const float2* gx = (const float2*)(g_OX + obase * (N * N));
            const float2* gm = (const float2*)(g_OM + obase * (N * N));
            for (int i2 = tid; i2 < 512; i2 += 256) {
                int r = i2 >> 4, c = (i2 & 15) * 2;
                *(float2*)(sX + r * MA + c) = gx[i2];
                *(float2*)(sMm + r * MA + c) = gm[i2];
            }
            if (tid < N) sc[tid] = g_Oc[obase * N + tid];
        }
        __syncthreads();

        // region1: W = S*X ; muN = c + X^T mu
        {
            const float2* Sr0 = (const float2*)(sS + r0 * MA);
            const float2* Sr1 = (const float2*)(sS + (r0 + 1) * MA);
            float a00 = 0, a01 = 0, a10 = 0, a11 = 0;
            #pragma unroll
            for (int k2 = 0; k2 < 16; k2++) {
                float2 x0 = Sr0[k2], x1 = Sr1[k2];
                float2 y0 = *(const float2*)(sX + (2 * k2) * MA + c0);
                float2 y1 = *(const float2*)(sX + (2 * k2 + 1) * MA + c0);
                a00 += x0.x * y0.x + x0.y * y1.x;  a01 += x0.x * y0.y + x0.y * y1.y;
                a10 += x1.x * y0.x + x1.y * y1.x;  a11 += x1.x * y0.y + x1.y * y1.y;
            }
            *(float2*)(sW + r0 * MA + c0) = make_float2(a00, a01);
            *(float2*)(sW + (r0 + 1) * MA + c0) = make_float2(a10, a11);
        }
        if (tid < N) {
            float s = sc[tid];
            #pragma unroll
            for (int j = 0; j < N; j++) s += sX[j * MA + tid] * smu[j];
            smuN[tid] = s;
        }
        __syncthreads();

        // region2: S' = M + X^T W -> sS ; store entry_k
        {
            float2 f0 = *(const float2*)(sMm + r0 * MA + c0);
            float2 f1 = *(const float2*)(sMm + (r0 + 1) * MA + c0);
            float a00 = f0.x, a01 = f0.y, a10 = f1.x, a11 = f1.y;
            #pragma unroll
            for (int j = 0; j < N; j++) {
                float2 xj = *(const float2*)(sX + j * MA + r0);
                float2 wj = *(const float2*)(sW + j * MA + c0);
                a00 += xj.x * wj.x;  a01 += xj.x * wj.y;
                a10 += xj.y * wj.x;  a11 += xj.y * wj.y;
            }
            *(float2*)(sS + r0 * MA + c0) = make_float2(a00, a01);
            *(float2*)(sS + (r0 + 1) * MA + c0) = make_float2(a10, a11);
            float* ge = g_eS + ((size_t)b * NCH + k) * (N * N);
            *(float2*)(ge + r0 * 32 + c0) = make_float2(a00, a01);
            *(float2*)(ge + (r0 + 1) * 32 + c0) = make_float2(a10, a11);
        }
        if (tid < N) {
            smu[tid] = smuN[tid];
            g_emu[((size_t)b * NCH + k) * N + tid] = smuN[tid];
        }
        __syncthreads();
    }
}

// =====================================================================
// Kernel 5 (Phase C): per-chunk backward recursion. grid (8, 64), 256 thr.
// =====================================================================
__global__ __launch_bounds__(256) void k_scanC(float* __restrict__ out)
{
    const int k = blockIdx.x, b = blockIdx.y;
    const int t_lo = CHS * k;
    const int t_hi = (k == NCH - 1) ? (T - 2) : (CHS * k + CHS - 1);
    const int tid = threadIdx.x;

    __shared__ __align__(16) float sS[N * MA], sX[N * MA], sMm[N * MA], sW[N * MA];
    __shared__ float smu[N], smuN[N], sc[N];

    const int r0 = (tid >> 4) * 2, c0 = (tid & 15) * 2;

    {
        const size_t ebase = (size_t)b * NCH + k;
        const float2* ge = (const float2*)(g_eS + ebase * (N * N));
        for (int i2 = tid; i2 < 512; i2 += 256) {
            int r = i2 >> 4, c = (i2 & 15) * 2;
            *(float2*)(sS + r * MA + c) = ge[i2];
        }
        if (tid < N) smu[tid] = g_emu[ebase * N + tid];
    }
    __syncthreads();

    for (int t = t_hi; t >= t_lo; t--) {
        const size_t base = (size_t)b * (T - 1) + t;
        const size_t bt = (size_t)b * T + t;
        {
            const float2* gx = (const float2*)(g_J + base * (N * N));
            const float2* gm = (const float2*)(g_M + base * (N * N));
            for (int i2 = tid; i2 < 512; i2 += 256) {
                int r = i2 >> 4, c = (i2 & 15) * 2;
                *(float2*)(sX + r * MA + c) = gx[i2];
                *(float2*)(sMm + r * MA + c) = gm[i2];
            }
            if (tid < N) sc[tid] = g_c[base * N + tid];
        }
        __syncthreads();

        // region1: W = S*X ; muN = c + X^T mu
        {
            const float2* Sr0 = (const float2*)(sS + r0 * MA);
            const float2* Sr1 = (const float2*)(sS + (r0 + 1) * MA);
            float a00 = 0, a01 = 0, a10 = 0, a11 = 0;
            #pragma unroll
            for (int k2 = 0; k2 < 16; k2++) {
                float2 x0 = Sr0[k2], x1 = Sr1[k2];
                float2 y0 = *(const float2*)(sX + (2 * k2) * MA + c0);
                float2 y1 = *(const float2*)(sX + (2 * k2 + 1) * MA + c0);
                a00 += x0.x * y0.x + x0.y * y1.x;  a01 += x0.x * y0.y + x0.y * y1.y;
                a10 += x1.x * y0.x + x1.y * y1.x;  a11 += x1.x * y0.y + x1.y * y1.y;
            }
            *(float2*)(sW + r0 * MA + c0) = make_float2(a00, a01);
            *(float2*)(sW + (r0 + 1) * MA + c0) = make_float2(a10, a11);
        }
        if (tid < N) {
            float s = sc[tid];
            #pragma unroll
            for (int j = 0; j < N; j++) s += sX[j * MA + tid] * smu[j];
            smuN[tid] = s;
        }
        __syncthreads();

        // region2: S' = M + X^T W -> sS ; write outputs
        {
            float2 f0 = *(const float2*)(sMm + r0 * MA + c0);
            float2 f1 = *(const float2*)(sMm + (r0 + 1) * MA + c0);
            float a00 = f0.x, a01 = f0.y, a10 = f1.x, a11 = f1.y;
            #pragma unroll
            for (int j = 0; j < N; j++) {
                float2 xj = *(const float2*)(sX + j * MA + r0);
                float2 wj = *(const float2*)(sW + j * MA + c0);
                a00 += xj.x * wj.x;  a01 += xj.x * wj.y;
                a10 += xj.y * wj.x;  a11 += xj.y * wj.y;
            }
            *(float2*)(sS + r0 * MA + c0) = make_float2(a00, a01);
            *(float2*)(sS + (r0 + 1) * MA + c0) = make_float2(a10, a11);
            float* o = out + (bt * N + r0) * (N + 1) + 1 + c0;
            o[0] = a00; o[1] = a01;
            o[N + 1] = a10; o[N + 2] = a11;
        }
        if (tid < N) {
            smu[tid] = smuN[tid];
            out[(bt * N + tid) * (N + 1)] = smuN[tid];
        }
        __syncthreads();
    }
}

extern "C" void kernel_launch(void* const* d_in, const int* in_sizes, int n_in,
                              void* d_out, int out_size) {
    (void)in_sizes; (void)n_in; (void)out_size;
    const float* Y   = (const float*)d_in[0];
    const float* U   = (const float*)d_in[1];
    const float* A   = (const float*)d_in[2];
    const float* Bm  = (const float*)d_in[3];
    const float* C   = (const float*)d_in[4];
    const float* mu0 = (const float*)d_in[5];
    const float* S0  = (const float*)d_in[6];
    float* out = (float*)d_out;

    k_fwd<<<BATCH, 256>>>(Y, U, A, Bm, C, mu0, S0);
    k_J2<<<dim3(T - 1, BATCH), 128>>>(A);
    k_scanA<<<dim3(NCH, BATCH), 256>>>();
    k_scanB<<<BATCH, 256>>>(out);
    k_scanC<<<dim3(NCH, BATCH), 256>>>(out);
}

// round 5
// speedup vs baseline: 1.2367x; 1.2367x over previous
#include <cuda_runtime.h>

#define BATCH 64
#define T 128
#define N 32
#define M 8
#define P 16
#define MA 34    // padded row stride (even -> float2-aligned rows)
#define NCH 8    // backward-scan chunks
#define CHS 16   // chunk size
#define NTF 512  // k_fwd threads

// Global scratch
__device__ float g_muf[BATCH * T * N];
__device__ float g_mup[BATCH * T * N];
__device__ float g_Sigf[(size_t)BATCH * T * N * N];
__device__ float g_Sigp[(size_t)BATCH * T * N * N];
__device__ float g_J[(size_t)BATCH * (T - 1) * N * N];   // X_t = J_t^T
__device__ float g_M[(size_t)BATCH * (T - 1) * N * N];   // M_t
__device__ float g_c[(size_t)BATCH * (T - 1) * N];       // c_t
__device__ float g_OX[(size_t)BATCH * NCH * N * N];      // chunk op X
__device__ float g_OM[(size_t)BATCH * NCH * N * N];      // chunk op M
__device__ float g_Oc[(size_t)BATCH * NCH * N];          // chunk op c
__device__ float g_eS[(size_t)BATCH * NCH * N * N];      // chunk entry Sigma
__device__ float g_emu[(size_t)BATCH * NCH * N];         // chunk entry mu

// =====================================================================
// Kernel 1: forward Kalman filter. One CTA (512 thr) per batch element.
// =====================================================================
__global__ __launch_bounds__(NTF, 1) void k_fwd(
    const float* __restrict__ Y, const float* __restrict__ U,
    const float* __restrict__ A, const float* __restrict__ Bm,
    const float* __restrict__ C, const float* __restrict__ mu0,
    const float* __restrict__ Sig0)
{
    const int b = blockIdx.x;
    const int tid = threadIdx.x;

    __shared__ __align__(16) float sA[2][N * MA];
    __shared__ __align__(16) float sC[2][P * MA];
    __shared__ __align__(16) float sB[2][N * M];
    __shared__ float sy[2][P], su[2][M];
    __shared__ __align__(16) float sSig[N * MA], sAS[N * MA], sSigp[N * MA];
    __shared__ __align__(16) float sCSp[P * MA];
    __shared__ __align__(16) float sS[P * 18];
    __shared__ __align__(16) float sX[P * MA];     // X = K^T (16 x 32)
    __shared__ float smu[N], smup[N], sd[P];

    if (tid < N) smu[tid] = mu0[tid];
    for (int i2 = tid; i2 < 512; i2 += NTF) {
        int r = i2 >> 4, c2 = i2 & 15;
        *(float2*)(sSig + r * MA + 2 * c2) = ((const float2*)Sig0)[i2];
    }
    {
        const size_t bt = (size_t)b * T;
        const float2* Ab = (const float2*)(A + bt * (N * N));
        const float2* Cb = (const float2*)(C + bt * (P * N));
        const float2* Bb = (const float2*)(Bm + bt * (N * M));
        for (int i2 = tid; i2 < 512; i2 += NTF) {
            int r = i2 >> 4, c2 = i2 & 15;
            *(float2*)(sA[0] + r * MA + 2 * c2) = Ab[i2];
        }
        if (tid < 256) {
            int r = tid >> 4, c2 = tid & 15;
            *(float2*)(sC[0] + r * MA + 2 * c2) = Cb[tid];
        }
        if (tid < 128) ((float2*)sB[0])[tid] = Bb[tid];
        if (tid < P) sy[0][tid] = Y[bt * P + tid];
        if (tid < M) su[0][tid] = U[bt * M + tid];
    }
    __syncthreads();

    // 1x2 tile: row r, cols c0,c0+1
    const int r = tid >> 4, c0 = (tid & 15) * 2;

    for (int t = 0; t < T; t++) {
        const int cur = t & 1, nxt = cur ^ 1;
        const size_t bt = (size_t)b * T + t;
        const float* Ac = sA[cur];
        const float* Cc = sC[cur];

        // ---- R0: mu_p (warp0) + AS = A*Sig ----
        if (tid < N) {
            const float2* Ar = (const float2*)(Ac + tid * MA);
            float s = 0.f;
            #pragma unroll
            for (int j = 0; j < 16; j++) {
                float2 a = Ar[j];
                s += a.x * smu[2 * j] + a.y * smu[2 * j + 1];
            }
            const float2* Br = (const float2*)(sB[cur] + tid * M);
            #pragma unroll
            for (int j = 0; j < 4; j++) {
                float2 bb = Br[j];
                s += bb.x * su[cur][2 * j] + bb.y * su[cur][2 * j + 1];
            }
            smup[tid] = s;
            g_mup[bt * N + tid] = s;
        }
        {
            const float2* Xr = (const float2*)(Ac + r * MA);
            float a0 = 0, a1 = 0;
            #pragma unroll
            for (int k2 = 0; k2 < 16; k2++) {
                float2 x = Xr[k2];
                float2 y0 = *(const float2*)(sSig + (2 * k2) * MA + c0);
                float2 y1 = *(const float2*)(sSig + (2 * k2 + 1) * MA + c0);
                a0 += x.x * y0.x + x.y * y1.x;
                a1 += x.x * y0.y + x.y * y1.y;
            }
            *(float2*)(sAS + r * MA + c0) = make_float2(a0, a1);
        }
        __syncthreads();

        // ---- R1: Sig_p = AS * A^T + Q ----
        {
            const float2* Xr = (const float2*)(sAS + r * MA);
            const float2* Yc0 = (const float2*)(Ac + c0 * MA);
            const float2* Yc1 = (const float2*)(Ac + (c0 + 1) * MA);
            float a0 = (r == c0) ? 0.01f : 0.f;
            float a1 = (r == c0 + 1) ? 0.01f : 0.f;
            #pragma unroll
            for (int k2 = 0; k2 < 16; k2++) {
                float2 x = Xr[k2], y0 = Yc0[k2], y1 = Yc1[k2];
                a0 += x.x * y0.x + x.y * y0.y;
                a1 += x.x * y1.x + x.y * y1.y;
            }
            *(float2*)(sSigp + r * MA + c0) = make_float2(a0, a1);
        }
        __syncthreads();

        // ---- R2: CSp = C*Sig_p (tid<256) | resid (256..271) ----
        if (tid < 256) {
            const int rr = tid >> 4, cc = (tid & 15) * 2;
            const float2* Xr = (const float2*)(Cc + rr * MA);
            float a0 = 0, a1 = 0;
            #pragma unroll
            for (int k2 = 0; k2 < 16; k2++) {
                float2 x = Xr[k2];
                float2 y0 = *(const float2*)(sSigp + (2 * k2) * MA + cc);
                float2 y1 = *(const float2*)(sSigp + (2 * k2 + 1) * MA + cc);
                a0 += x.x * y0.x + x.y * y1.x;
                a1 += x.x * y0.y + x.y * y1.y;
            }
            *(float2*)(sCSp + rr * MA + cc) = make_float2(a0, a1);
        } else if (tid < 272) {
            const int i = tid - 256;
            const float2* Cr = (const float2*)(Cc + i * MA);
            float s = sy[cur][i];
            #pragma unroll
            for (int j = 0; j < 16; j++) {
                float2 cv = Cr[j];
                s -= cv.x * smup[2 * j] + cv.y * smup[2 * j + 1];
            }
            sd[i] = s;
        }
        __syncthreads();

        // ---- R3: S = CSp*C^T + R (tid<128) | STG Sig_p (tid>=128) ----
        if (tid < 128) {
            const int rr = tid >> 3, cc = (tid & 7) * 2;
            const float2* Xr = (const float2*)(sCSp + rr * MA);
            const float2* Yc0 = (const float2*)(Cc + cc * MA);
            const float2* Yc1 = (const float2*)(Cc + (cc + 1) * MA);
            float a0 = (rr == cc) ? 0.01f : 0.f;
            float a1 = (rr == cc + 1) ? 0.01f : 0.f;
            #pragma unroll
            for (int k2 = 0; k2 < 16; k2++) {
                float2 x = Xr[k2], y0 = Yc0[k2], y1 = Yc1[k2];
                a0 += x.x * y0.x + x.y * y0.y;
                a1 += x.x * y1.x + x.y * y1.y;
            }
            *(float2*)(sS + rr * 18 + cc) = make_float2(a0, a1);
        } else {
            float2* gp = (float2*)(g_Sigp + (bt << 10));
            for (int i2 = tid - 128; i2 < 512; i2 += 384) {
                int rr = i2 >> 4, c2 = i2 & 15;
                gp[i2] = *(const float2*)(sSigp + rr * MA + 2 * c2);
            }
        }
        __syncthreads();

        // ---- R4: warp0 solves S X = CSp; warps 1-15 prefetch t+1 ----
        if (tid < 32) {
            const int c = tid;
            float Sc[P], Rc[P], piv[P];
            #pragma unroll
            for (int rr = 0; rr < P; rr++) {
                Sc[rr] = sS[rr * 18 + (c & 15)];
                Rc[rr] = sCSp[rr * MA + c];
            }
            #pragma unroll
            for (int j = 0; j < P; j++) {
                float f[P];
                #pragma unroll
                for (int rr = 0; rr < P; rr++) f[rr] = __shfl_sync(0xffffffffu, Sc[rr], j);
                float pinv = 1.0f / f[j];
                piv[j] = f[j];
                float sj = Sc[j] * pinv, rj = Rc[j] * pinv;
                #pragma unroll
                for (int rr = 0; rr < P; rr++) {
                    if (rr != j) { Sc[rr] -= f[rr] * sj; Rc[rr] -= f[rr] * rj; }
                }
            }
            #pragma unroll
            for (int rr = 0; rr < P; rr++) sX[rr * MA + c] = Rc[rr] / piv[rr];
        } else if (t + 1 < T) {
            const int pt = tid - 32;
            const size_t bt1 = bt + 1;
            const float2* An = (const float2*)(A + bt1 * (N * N));
            const float2* Cn = (const float2*)(C + bt1 * (P * N));
            const float2* Bn = (const float2*)(Bm + bt1 * (N * M));
            for (int i2 = pt; i2 < 512; i2 += 480) {
                int rr = i2 >> 4, c2 = i2 & 15;
                *(float2*)(sA[nxt] + rr * MA + 2 * c2) = An[i2];
            }
            if (pt < 256) {
                int rr = pt >> 4, c2 = pt & 15;
                *(float2*)(sC[nxt] + rr * MA + 2 * c2) = Cn[pt];
            }
            if (pt < 128) ((float2*)sB[nxt])[pt] = Bn[pt];
            if (pt < P) sy[nxt][pt] = Y[bt1 * P + pt];
            else if (pt < P + M) su[nxt][pt - P] = U[bt1 * M + (pt - P)];
        }
        __syncthreads();

        // ---- R5: mu_f (warp0) + Sf = Sigp - 0.5*(X^T Z + Z^T X), fused sym ----
        if (tid < N) {
            float s = smup[tid];
            #pragma unroll
            for (int j = 0; j < P; j++) s += sX[j * MA + tid] * sd[j];
            smu[tid] = s;
            g_muf[bt * N + tid] = s;
        }
        {
            float2 p = *(const float2*)(sSigp + r * MA + c0);
            float m0 = 0, m1 = 0;
            #pragma unroll
            for (int j = 0; j < P; j++) {
                float xr = sX[j * MA + r];
                float zr = sCSp[j * MA + r];
                float2 xc = *(const float2*)(sX + j * MA + c0);
                float2 zc = *(const float2*)(sCSp + j * MA + c0);
                m0 += xr * zc.x + zr * xc.x;
                m1 += xr * zc.y + zr * xc.y;
            }
            float v0 = p.x - 0.5f * m0, v1 = p.y - 0.5f * m1;
            *(float2*)(sSig + r * MA + c0) = make_float2(v0, v1);
            float* gf = g_Sigf + (bt << 10);
            *(float2*)(gf + r * 32 + c0) = make_float2(v0, v1);
        }
        __syncthreads();
    }
}

// =====================================================================
// Kernel 2: per (b,t) compute X_t = J_t^T, M_t, c_t. grid (127, 64), 128 thr.
// Solve done by warp0 in registers (normalized Gauss-Jordan, SPD -> no pivot).
// =====================================================================
__global__ __launch_bounds__(128) void k_J2(const float* __restrict__ A)
{
    const int t = blockIdx.x;      // 0..126
    const int b = blockIdx.y;
    const size_t bt = (size_t)b * T + t;
    const int tid = threadIdx.x;

    __shared__ __align__(16) float sA[N * MA], sSf[N * MA], sSp[N * MA];
    __shared__ __align__(16) float sG[N * MA], sXs[N * MA];
    __shared__ float smf[N], smp[N];

    {
        const float2* Ab = (const float2*)(A + bt * (N * N));
        const float2* gf = (const float2*)(g_Sigf + (bt << 10));
        const float2* gp = (const float2*)(g_Sigp + ((bt + 1) << 10));
        for (int i2 = tid; i2 < 512; i2 += 128) {
            int r = i2 >> 4, c = (i2 & 15) * 2;
            *(float2*)(sA + r * MA + c) = Ab[i2];
            *(float2*)(sSf + r * MA + c) = gf[i2];
            *(float2*)(sSp + r * MA + c) = gp[i2];
        }
        if (tid < N) {
            smf[tid] = g_muf[bt * N + tid];
            smp[tid] = g_mup[(bt + 1) * N + tid];
        }
    }
    __syncthreads();

    // G = A * Sf (2x2 tiles, 2 per thread)
    #pragma unroll
    for (int s = 0; s < 2; s++) {
        const int id = tid + s * 128;
        const int r0 = (id >> 4) * 2, c0 = (id & 15) * 2;
        const float2* Xr0 = (const float2*)(sA + r0 * MA);
        const float2* Xr1 = (const float2*)(sA + (r0 + 1) * MA);
        float a00 = 0, a01 = 0, a10 = 0, a11 = 0;
        #pragma unroll
        for (int k2 = 0; k2 < 16; k2++) {
            float2 x0 = Xr0[k2], x1 = Xr1[k2];
            float2 y0 = *(const float2*)(sSf + (2 * k2) * MA + c0);
            float2 y1 = *(const float2*)(sSf + (2 * k2 + 1) * MA + c0);
            a00 += x0.x * y0.x + x0.y * y1.x;  a01 += x0.x * y0.y + x0.y * y1.y;
            a10 += x1.x * y0.x + x1.y * y1.x;  a11 += x1.x * y0.y + x1.y * y1.y;
        }
        *(float2*)(sG + r0 * MA + c0) = make_float2(a00, a01);
        *(float2*)(sG + (r0 + 1) * MA + c0) = make_float2(a10, a11);
    }
    __syncthreads();

    // warp0: register GJ  Sp X = G  (lane c holds column c of Sp and of G)
    if (tid < 32) {
        const int c = tid;
        float Sc[N], Gc[N];
        #pragma unroll
        for (int rr = 0; rr < N; rr++) {
            Sc[rr] = sSp[rr * MA + c];
            Gc[rr] = sG[rr * MA + c];
        }
        #pragma unroll
        for (int j = 0; j < N; j++) {
            float fj = __shfl_sync(0xffffffffu, Sc[j], j);
            float pinv = 1.0f / fj;
            Sc[j] *= pinv;
            Gc[j] *= pinv;
            float scj = Sc[j], gcj = Gc[j];
            #pragma unroll
            for (int rr = 0; rr < N; rr++) {
                if (rr != j) {
                    float f = __shfl_sync(0xffffffffu, Sc[rr], j);
                    Sc[rr] -= f * scj;
                    Gc[rr] -= f * gcj;
                }
            }
        }
        #pragma unroll
        for (int rr = 0; rr < N; rr++) sXs[rr * MA + c] = Gc[rr];
    }
    __syncthreads();

    const size_t jidx = (size_t)b * (T - 1) + t;

    // c = mf - X^T mp
    if (tid < N) {
        float s = smf[tid];
        #pragma unroll
        for (int k = 0; k < N; k++) s -= sXs[k * MA + tid] * smp[k];
        g_c[jidx * N + tid] = s;
    }
    // g_J <- X (float2, coalesced)
    {
        float2* gj = (float2*)(g_J + jidx * (N * N));
        for (int i2 = tid; i2 < 512; i2 += 128) {
            int r = i2 >> 4, c = (i2 & 15) * 2;
            gj[i2] = *(const float2*)(sXs + r * MA + c);
        }
    }
    // M = Sf - X^T G  (symmetric in exact arithmetic)
    {
        float* gm = g_M + jidx * (N * N);
        #pragma unroll
        for (int s = 0; s < 2; s++) {
            const int id = tid + s * 128;
            const int r0 = (id >> 4) * 2, c0 = (id & 15) * 2;
            float2 f0 = *(const float2*)(sSf + r0 * MA + c0);
            float2 f1 = *(const float2*)(sSf + (r0 + 1) * MA + c0);
            float a00 = f0.x, a01 = f0.y, a10 = f1.x, a11 = f1.y;
            #pragma unroll
            for (int k = 0; k < N; k++) {
                float x0 = sXs[k * MA + r0], x1 = sXs[k * MA + r0 + 1];
                float2 g = *(const float2*)(sG + k * MA + c0);
                a00 -= x0 * g.x;  a01 -= x0 * g.y;
                a10 -= x1 * g.x;  a11 -= x1 * g.y;
            }
            *(float2*)(gm + r0 * 32 + c0) = make_float2(a00, a01);
            *(float2*)(gm + (r0 + 1) * 32 + c0) = make_float2(a10, a11);
        }
    }
}

// =====================================================================
// Kernel 3 (Phase A): compose chunk operators. grid (8, 64), 256 thr.
// =====================================================================
__global__ __launch_bounds__(256) void k_scanA()
{
    const int k = blockIdx.x, b = blockIdx.y;
    const int t_lo = CHS * k;
    const int t_hi = (k == NCH - 1) ? (T - 2) : (CHS * k + CHS - 1);
    const int tid = threadIdx.x;

    __shared__ __align__(16) float sXO[N * MA], sMO[N * MA];
    __shared__ __align__(16) float sXt[N * MA], sMt[N * MA];
    __shared__ __align__(16) float sW[N * MA], sXN[N * MA];
    __shared__ float scO[N], sct[N], scN[N];

    const int r0 = (tid >> 4) * 2, c0 = (tid & 15) * 2;

    {
        const size_t base = (size_t)b * (T - 1) + t_hi;
        const float2* gx = (const float2*)(g_J + base * (N * N));
        const float2* gm = (const float2*)(g_M + base * (N * N));
        for (int i2 = tid; i2 < 512; i2 += 256) {
            int r = i2 >> 4, c = (i2 & 15) * 2;
            *(float2*)(sXO + r * MA + c) = gx[i2];
            *(float2*)(sMO + r * MA + c) = gm[i2];
        }
        if (tid < N) scO[tid] = g_c[base * N + tid];
    }
    __syncthreads();

    for (int t = t_hi - 1; t >= t_lo; t--) {
        const size_t base = (size_t)b * (T - 1) + t;
        {
            const float2* gx = (const float2*)(g_J + base * (N * N));
            const float2* gm = (const float2*)(g_M + base * (N * N));
            for (int i2 = tid; i2 < 512; i2 += 256) {
                int r = i2 >> 4, c = (i2 & 15) * 2;
                *(float2*)(sXt + r * MA + c) = gx[i2];
                *(float2*)(sMt + r * MA + c) = gm[i2];
            }
            if (tid < N) sct[tid] = g_c[base * N + tid];
        }
        __syncthreads();

        {
            const float2* Mr0 = (const float2*)(sMO + r0 * MA);
            const float2* Mr1 = (const float2*)(sMO + (r0 + 1) * MA);
            const float2* Or0 = (const float2*)(sXO + r0 * MA);
            const float2* Or1 = (const float2*)(sXO + (r0 + 1) * MA);
            float w00 = 0, w01 = 0, w10 = 0, w11 = 0;
            float x00 = 0, x01 = 0, x10 = 0, x11 = 0;
            #pragma unroll
            for (int k2 = 0; k2 < 16; k2++) {
                float2 y0 = *(const float2*)(sXt + (2 * k2) * MA + c0);
                float2 y1 = *(const float2*)(sXt + (2 * k2 + 1) * MA + c0);
                float2 m0 = Mr0[k2], m1 = Mr1[k2];
                float2 o0 = Or0[k2], o1 = Or1[k2];
                w00 += m0.x * y0.x + m0.y * y1.x;  w01 += m0.x * y0.y + m0.y * y1.y;
                w10 += m1.x * y0.x + m1.y * y1.x;  w11 += m1.x * y0.y + m1.y * y1.y;
                x00 += o0.x * y0.x + o0.y * y1.x;  x01 += o0.x * y0.y + o0.y * y1.y;
                x10 += o1.x * y0.x + o1.y * y1.x;  x11 += o1.x * y0.y + o1.y * y1.y;
            }
            *(float2*)(sW + r0 * MA + c0) = make_float2(w00, w01);
            *(float2*)(sW + (r0 + 1) * MA + c0) = make_float2(w10, w11);
            *(float2*)(sXN + r0 * MA + c0) = make_float2(x00, x01);
            *(float2*)(sXN + (r0 + 1) * MA + c0) = make_float2(x10, x11);
        }
        if (tid < N) {
            float s = sct[tid];
            #pragma unroll
            for (int j = 0; j < N; j++) s += sXt[j * MA + tid] * scO[j];
            scN[tid] = s;
        }
        __syncthreads();

        {
            float2 f0 = *(const float2*)(sMt + r0 * MA + c0);
            float2 f1 = *(const float2*)(sMt + (r0 + 1) * MA + c0);
            float a00 = f0.x, a01 = f0.y, a10 = f1.x, a11 = f1.y;
            #pragma unroll
            for (int j = 0; j < N; j++) {
                float2 xj = *(const float2*)(sXt + j * MA + r0);
                float2 wj = *(const float2*)(sW + j * MA + c0);
                a00 += xj.x * wj.x;  a01 += xj.x * wj.y;
                a10 += xj.y * wj.x;  a11 += xj.y * wj.y;
            }
            *(float2*)(sMO + r0 * MA + c0) = make_float2(a00, a01);
            *(float2*)(sMO + (r0 + 1) * MA + c0) = make_float2(a10, a11);
            *(float2*)(sXO + r0 * MA + c0) = *(const float2*)(sXN + r0 * MA + c0);
            *(float2*)(sXO + (r0 + 1) * MA + c0) = *(const float2*)(sXN + (r0 + 1) * MA + c0);
        }
        if (tid < N) scO[tid] = scN[tid];
        __syncthreads();
    }

    {
        const size_t obase = (size_t)b * NCH + k;
        float2* gx = (float2*)(g_OX + obase * (N * N));
        float2* gm = (float2*)(g_OM + obase * (N * N));
        for (int i2 = tid; i2 < 512; i2 += 256) {
            int r = i2 >> 4, c = (i2 & 15) * 2;
            gx[i2] = *(const float2*)(sXO + r * MA + c);
            gm[i2] = *(const float2*)(sMO + r * MA + c);
        }
        if (tid < N) g_Oc[obase * N + tid] = scO[tid];
    }
}

// =====================================================================
// Kernel 4 (Phase B): boundary states per batch. grid 64, 256 thr.
// =====================================================================
__global__ __launch_bounds__(256) void k_scanB(float* __restrict__ out)
{
    const int b = blockIdx.x;
    const int tid = threadIdx.x;

    __shared__ __align__(16) float sS[N * MA], sX[N * MA], sMm[N * MA], sW[N * MA];
    __shared__ float smu[N], smuN[N], sc[N];

    const int r0 = (tid >> 4) * 2, c0 = (tid & 15) * 2;

    {
        const size_t btL = (size_t)b * T + (T - 1);
        const float2* gf = (const float2*)(g_Sigf + (btL << 10));
        float2* ge = (float2*)(g_eS + ((size_t)b * NCH + (NCH - 1)) * (N * N));
        for (int i2 = tid; i2 < 512; i2 += 256) {
            int r = i2 >> 4, c = (i2 & 15) * 2;
            float2 v = gf[i2];
            *(float2*)(sS + r * MA + c) = v;
            ge[i2] = v;
            float* o = out + (btL * N + r) * (N + 1) + 1 + c;
            o[0] = v.x; o[1] = v.y;
        }
        if (tid < N) {
            float v = g_muf[btL * N + tid];
            smu[tid] = v;
            g_emu[((size_t)b * NCH + (NCH - 1)) * N + tid] = v;
            out[(btL * N + tid) * (N + 1)] = v;
        }
    }
    __syncthreads();

    for (int k = NCH - 2; k >= 0; k--) {
        const size_t obase = (size_t)b * NCH + (k + 1);
        {
            const float2* gx = (const float2*)(g_OX + obase * (N * N));
            const float2* gm = (const float2*)(g_OM + obase * (N * N));
            for (int i2 = tid; i2 < 512; i2 += 256) {
                int r = i2 >> 4, c = (i2 & 15) * 2;
                *(float2*)(sX + r * MA + c) = gx[i2];
                *(float2*)(sMm + r * MA + c) = gm[i2];
            }
            if (tid < N) sc[tid] = g_Oc[obase * N + tid];
        }
        __syncthreads();

        {
            const float2* Sr0 = (const float2*)(sS + r0 * MA);
            const float2* Sr1 = (const float2*)(sS + (r0 + 1) * MA);
            float a00 = 0, a01 = 0, a10 = 0, a11 = 0;
            #pragma unroll
            for (int k2 = 0; k2 < 16; k2++) {
                float2 x0 = Sr0[k2], x1 = Sr1[k2];
                float2 y0 = *(const float2*)(sX + (2 * k2) * MA + c0);
                float2 y1 = *(const float2*)(sX + (2 * k2 + 1) * MA + c0);
                a00 += x0.x * y0.x + x0.y * y1.x;  a01 += x0.x * y0.y + x0.y * y1.y;
                a10 += x1.x * y0.x + x1.y * y1.x;  a11 += x1.x * y0.y + x1.y * y1.y;
            }
            *(float2*)(sW + r0 * MA + c0) = make_float2(a00, a01);
            *(float2*)(sW + (r0 + 1) * MA + c0) = make_float2(a10, a11);
        }
        if (tid < N) {
            float s = sc[tid];
            #pragma unroll
            for (int j = 0; j < N; j++) s += sX[j * MA + tid] * smu[j];
            smuN[tid] = s;
        }
        __syncthreads();

        {
            float2 f0 = *(const float2*)(sMm + r0 * MA + c0);
            float2 f1 = *(const float2*)(sMm + (r0 + 1) * MA + c0);
            float a00 = f0.x, a01 = f0.y, a10 = f1.x, a11 = f1.y;
            #pragma unroll
            for (int j = 0; j < N; j++) {
                float2 xj = *(const float2*)(sX + j * MA + r0);
                float2 wj = *(const float2*)(sW + j * MA + c0);
                a00 += xj.x * wj.x;  a01 += xj.x * wj.y;
                a10 += xj.y * wj.x;  a11 += xj.y * wj.y;
            }
            *(float2*)(sS + r0 * MA + c0) = make_float2(a00, a01);
            *(float2*)(sS + (r0 + 1) * MA + c0) = make_float2(a10, a11);
            float* ge = g_eS + ((size_t)b * NCH + k) * (N * N);
            *(float2*)(ge + r0 * 32 + c0) = make_float2(a00, a01);
            *(float2*)(ge + (r0 + 1) * 32 + c0) = make_float2(a10, a11);
        }
        if (tid < N) {
            smu[tid] = smuN[tid];
            g_emu[((size_t)b * NCH + k) * N + tid] = smuN[tid];
        }
        __syncthreads();
    }
}

// =====================================================================
// Kernel 5 (Phase C): per-chunk backward recursion. grid (8, 64), 256 thr.
// =====================================================================
__global__ __launch_bounds__(256) void k_scanC(float* __restrict__ out)
{
    const int k = blockIdx.x, b = blockIdx.y;
    const int t_lo = CHS * k;
    const int t_hi = (k == NCH - 1) ? (T - 2) : (CHS * k + CHS - 1);
    const int tid = threadIdx.x;

    __shared__ __align__(16) float sS[N * MA], sX[N * MA], sMm[N * MA], sW[N * MA];
    __shared__ float smu[N], smuN[N], sc[N];

    const int r0 = (tid >> 4) * 2, c0 = (tid & 15) * 2;

    {
        const size_t ebase = (size_t)b * NCH + k;
        const float2* ge = (const float2*)(g_eS + ebase * (N * N));
        for (int i2 = tid; i2 < 512; i2 += 256) {
            int r = i2 >> 4, c = (i2 & 15) * 2;
            *(float2*)(sS + r * MA + c) = ge[i2];
        }
        if (tid < N) smu[tid] = g_emu[ebase * N + tid];
    }
    __syncthreads();

    for (int t = t_hi; t >= t_lo; t--) {
        const size_t base = (size_t)b * (T - 1) + t;
        const size_t bt = (size_t)b * T + t;
        {
            const float2* gx = (const float2*)(g_J + base * (N * N));
            const float2* gm = (const float2*)(g_M + base * (N * N));
            for (int i2 = tid; i2 < 512; i2 += 256) {
                int r = i2 >> 4, c = (i2 & 15) * 2;
                *(float2*)(sX + r * MA + c) = gx[i2];
                *(float2*)(sMm + r * MA + c) = gm[i2];
            }
            if (tid < N) sc[tid] = g_c[base * N + tid];
        }
        __syncthreads();

        {
            const float2* Sr0 = (const float2*)(sS + r0 * MA);
            const float2* Sr1 = (const float2*)(sS + (r0 + 1) * MA);
            float a00 = 0, a01 = 0, a10 = 0, a11 = 0;
            #pragma unroll
            for (int k2 = 0; k2 < 16; k2++) {
                float2 x0 = Sr0[k2], x1 = Sr1[k2];
                float2 y0 = *(const float2*)(sX + (2 * k2) * MA + c0);
                float2 y1 = *(const float2*)(sX + (2 * k2 + 1) * MA + c0);
                a00 += x0.x * y0.x + x0.y * y1.x;  a01 += x0.x * y0.y + x0.y * y1.y;
                a10 += x1.x * y0.x + x1.y * y1.x;  a11 += x1.x * y0.y + x1.y * y1.y;
            }
            *(float2*)(sW + r0 * MA + c0) = make_float2(a00, a01);
            *(float2*)(sW + (r0 + 1) * MA + c0) = make_float2(a10, a11);
        }
        if (tid < N) {
            float s = sc[tid];
            #pragma unroll
            for (int j = 0; j < N; j++) s += sX[j * MA + tid] * smu[j];
            smuN[tid] = s;
        }
        __syncthreads();

        {
            float2 f0 = *(const float2*)(sMm + r0 * MA + c0);
            float2 f1 = *(const float2*)(sMm + (r0 + 1) * MA + c0);
            float a00 = f0.x, a01 = f0.y, a10 = f1.x, a11 = f1.y;
            #pragma unroll
            for (int j = 0; j < N; j++) {
                float2 xj = *(const float2*)(sX + j * MA + r0);
                float2 wj = *(const float2*)(sW + j * MA + c0);
                a00 += xj.x * wj.x;  a01 += xj.x * wj.y;
                a10 += xj.y * wj.x;  a11 += xj.y * wj.y;
            }
            *(float2*)(sS + r0 * MA + c0) = make_float2(a00, a01);
            *(float2*)(sS + (r0 + 1) * MA + c0) = make_float2(a10, a11);
            float* o = out + (bt * N + r0) * (N + 1) + 1 + c0;
            o[0] = a00; o[1] = a01;
            o[N + 1] = a10; o[N + 2] = a11;
        }
        if (tid < N) {
            smu[tid] = smuN[tid];
            out[(bt * N + tid) * (N + 1)] = smuN[tid];
        }
        __syncthreads();
    }
}

extern "C" void kernel_launch(void* const* d_in, const int* in_sizes, int n_in,
                              void* d_out, int out_size) {
    (void)in_sizes; (void)n_in; (void)out_size;
    const float* Y   = (const float*)d_in[0];
    const float* U   = (const float*)d_in[1];
    const float* A   = (const float*)d_in[2];
    const float* Bm  = (const float*)d_in[3];
    const float* C   = (const float*)d_in[4];
    const float* mu0 = (const float*)d_in[5];
    const float* S0  = (const float*)d_in[6];
    float* out = (float*)d_out;

    k_fwd<<<BATCH, NTF>>>(Y, U, A, Bm, C, mu0, S0);
    k_J2<<<dim3(T - 1, BATCH), 128>>>(A);
    k_scanA<<<dim3(NCH, BATCH), 256>>>();
    k_scanB<<<BATCH, 256>>>(out);
    k_scanC<<<dim3(NCH, BATCH), 256>>>(out);
}

// round 6
// speedup vs baseline: 1.2383x; 1.0012x over previous
#include <cuda_runtime.h>

#define BATCH 64
#define T 128
#define N 32
#define M 8
#define P 16
#define MA 34    // padded row stride (even -> float2-aligned rows)
#define NCH 8    // backward-scan chunks
#define CHS 16   // chunk size
#define NTF 512  // k_fwd threads

// Global scratch
__device__ float g_muf[BATCH * T * N];
__device__ float g_mup[BATCH * T * N];
__device__ float g_Sigf[(size_t)BATCH * T * N * N];
__device__ float g_Sigp[(size_t)BATCH * T * N * N];
__device__ float g_J[(size_t)BATCH * (T - 1) * N * N];   // X_t = J_t^T
__device__ float g_M[(size_t)BATCH * (T - 1) * N * N];   // M_t
__device__ float g_c[(size_t)BATCH * (T - 1) * N];       // c_t
__device__ float g_OX[(size_t)BATCH * NCH * N * N];      // chunk op X
__device__ float g_OM[(size_t)BATCH * NCH * N * N];      // chunk op M
__device__ float g_Oc[(size_t)BATCH * NCH * N];          // chunk op c
__device__ float g_eS[(size_t)BATCH * NCH * N * N];      // chunk entry Sigma
__device__ float g_emu[(size_t)BATCH * NCH * N];         // chunk entry mu

// =====================================================================
// Kernel 1: forward Kalman filter. One CTA (512 thr) per batch element.
// 5 regions/step; V = C*A trick overlaps innovation path with Sig_p.
// =====================================================================
__global__ __launch_bounds__(NTF, 1) void k_fwd(
    const float* __restrict__ Y, const float* __restrict__ U,
    const float* __restrict__ A, const float* __restrict__ Bm,
    const float* __restrict__ C, const float* __restrict__ mu0,
    const float* __restrict__ Sig0)
{
    const int b = blockIdx.x;
    const int tid = threadIdx.x;

    __shared__ __align__(16) float sA[2][N * MA];
    __shared__ __align__(16) float sC[2][P * MA];
    __shared__ __align__(16) float sB[2][N * M];
    __shared__ float sy[2][P], su[2][M];
    __shared__ __align__(16) float sSig[N * MA], sAS[N * MA], sSigp[N * MA];
    __shared__ __align__(16) float sV[P * MA], sZ[P * MA], sCSp[P * MA];
    __shared__ __align__(16) float sS[P * 18];
    __shared__ __align__(16) float sX[P * MA];     // X = K^T (16 x 32)
    __shared__ float smu[N], smup[N], sd[P];

    // ---- init state + t=0 inputs ----
    if (tid < N) smu[tid] = mu0[tid];
    for (int i2 = tid; i2 < 512; i2 += NTF) {
        int r = i2 >> 4, c2 = i2 & 15;
        *(float2*)(sSig + r * MA + 2 * c2) = ((const float2*)Sig0)[i2];
    }
    {
        const size_t bt = (size_t)b * T;
        const float2* Ab = (const float2*)(A + bt * (N * N));
        const float2* Cb = (const float2*)(C + bt * (P * N));
        const float2* Bb = (const float2*)(Bm + bt * (N * M));
        for (int i2 = tid; i2 < 512; i2 += NTF) {
            int r = i2 >> 4, c2 = i2 & 15;
            *(float2*)(sA[0] + r * MA + 2 * c2) = Ab[i2];
        }
        if (tid < 256) {
            int r = tid >> 4, c2 = tid & 15;
            *(float2*)(sC[0] + r * MA + 2 * c2) = Cb[tid];
        }
        if (tid < 128) ((float2*)sB[0])[tid] = Bb[tid];
        if (tid < P) sy[0][tid] = Y[bt * P + tid];
        if (tid < M) su[0][tid] = U[bt * M + tid];
    }
    __syncthreads();

    for (int t = 0; t < T; t++) {
        const int cur = t & 1, nxt = cur ^ 1;
        const size_t bt = (size_t)b * T + t;
        const float* Ac = sA[cur];
        const float* Cc = sC[cur];

        // ================= R0: AS = A*Sig (2x2) | V = C*A (1x2) + mu_p ======
        if (tid < 256) {
            const int r0 = (tid >> 4) * 2, c0 = (tid & 15) * 2;
            const float2* Xr0 = (const float2*)(Ac + r0 * MA);
            const float2* Xr1 = (const float2*)(Ac + (r0 + 1) * MA);
            float a00 = 0, a01 = 0, a10 = 0, a11 = 0;
            #pragma unroll
            for (int k2 = 0; k2 < 16; k2++) {
                float2 x0 = Xr0[k2], x1 = Xr1[k2];
                float2 y0 = *(const float2*)(sSig + (2 * k2) * MA + c0);
                float2 y1 = *(const float2*)(sSig + (2 * k2 + 1) * MA + c0);
                a00 += x0.x * y0.x + x0.y * y1.x;  a01 += x0.x * y0.y + x0.y * y1.y;
                a10 += x1.x * y0.x + x1.y * y1.x;  a11 += x1.x * y0.y + x1.y * y1.y;
            }
            *(float2*)(sAS + r0 * MA + c0) = make_float2(a00, a01);
            *(float2*)(sAS + (r0 + 1) * MA + c0) = make_float2(a10, a11);
        } else {
            const int id = tid - 256;
            const int i = id >> 4, j0 = (id & 15) * 2;
            const float2* Cr = (const float2*)(Cc + i * MA);
            float a0 = 0, a1 = 0;
            #pragma unroll
            for (int k2 = 0; k2 < 16; k2++) {
                float2 cv = Cr[k2];
                float2 y0 = *(const float2*)(Ac + (2 * k2) * MA + j0);
                float2 y1 = *(const float2*)(Ac + (2 * k2 + 1) * MA + j0);
                a0 += cv.x * y0.x + cv.y * y1.x;
                a1 += cv.x * y0.y + cv.y * y1.y;
            }
            *(float2*)(sV + i * MA + j0) = make_float2(a0, a1);
            if (id < 32) {      // mu_p for state row id
                const float2* Ar = (const float2*)(Ac + id * MA);
                float s = 0.f;
                #pragma unroll
                for (int j = 0; j < 16; j++) {
                    float2 a = Ar[j];
                    s += a.x * smu[2 * j] + a.y * smu[2 * j + 1];
                }
                const float2* Br = (const float2*)(sB[cur] + id * M);
                #pragma unroll
                for (int j = 0; j < 4; j++) {
                    float2 bb = Br[j];
                    s += bb.x * su[cur][2 * j] + bb.y * su[cur][2 * j + 1];
                }
                smup[id] = s;
                g_mup[bt * N + id] = s;
            }
        }
        __syncthreads();

        // ================= R1: Sig_p = AS*A^T + Q (2x2) | Z = V*Sig (1x2) ===
        if (tid < 256) {
            const int r0 = (tid >> 4) * 2, c0 = (tid & 15) * 2;
            const float2* Xr0 = (const float2*)(sAS + r0 * MA);
            const float2* Xr1 = (const float2*)(sAS + (r0 + 1) * MA);
            const float2* Yc0 = (const float2*)(Ac + c0 * MA);
            const float2* Yc1 = (const float2*)(Ac + (c0 + 1) * MA);
            float a00 = (r0 == c0) ? 0.01f : 0.f, a01 = 0, a10 = 0;
            float a11 = (r0 == c0) ? 0.01f : 0.f;
            #pragma unroll
            for (int k2 = 0; k2 < 16; k2++) {
                float2 x0 = Xr0[k2], x1 = Xr1[k2], y0 = Yc0[k2], y1 = Yc1[k2];
                a00 += x0.x * y0.x + x0.y * y0.y;  a01 += x0.x * y1.x + x0.y * y1.y;
                a10 += x1.x * y0.x + x1.y * y0.y;  a11 += x1.x * y1.x + x1.y * y1.y;
            }
            *(float2*)(sSigp + r0 * MA + c0) = make_float2(a00, a01);
            *(float2*)(sSigp + (r0 + 1) * MA + c0) = make_float2(a10, a11);
        } else {
            const int id = tid - 256;
            const int i = id >> 4, j0 = (id & 15) * 2;
            const float2* Vr = (const float2*)(sV + i * MA);
            float a0 = 0, a1 = 0;
            #pragma unroll
            for (int k2 = 0; k2 < 16; k2++) {
                float2 v = Vr[k2];
                float2 y0 = *(const float2*)(sSig + (2 * k2) * MA + j0);
                float2 y1 = *(const float2*)(sSig + (2 * k2 + 1) * MA + j0);
                a0 += v.x * y0.x + v.y * y1.x;
                a1 += v.x * y0.y + v.y * y1.y;
            }
            *(float2*)(sZ + i * MA + j0) = make_float2(a0, a1);
        }
        __syncthreads();

        // ==== R2: CSp = Z*A^T + 0.01C | S = Z*V^T + 0.01CC^T + R | resid | STG Sig_p
        if (tid < 256) {
            const int i = tid >> 4, j0 = (tid & 15) * 2;
            const float2* Zr = (const float2*)(sZ + i * MA);
            const float2* Aj0 = (const float2*)(Ac + j0 * MA);
            const float2* Aj1 = (const float2*)(Ac + (j0 + 1) * MA);
            float2 cv = *(const float2*)(Cc + i * MA + j0);
            float a0 = 0.01f * cv.x, a1 = 0.01f * cv.y;
            #pragma unroll
            for (int k2 = 0; k2 < 16; k2++) {
                float2 z = Zr[k2], y0 = Aj0[k2], y1 = Aj1[k2];
                a0 += z.x * y0.x + z.y * y0.y;
                a1 += z.x * y1.x + z.y * y1.y;
            }
            *(float2*)(sCSp + i * MA + j0) = make_float2(a0, a1);
        } else if (tid < 384) {
            const int id = tid - 256;
            const int i = id >> 3, j0 = (id & 7) * 2;
            const float2* Zr = (const float2*)(sZ + i * MA);
            const float2* Ci = (const float2*)(Cc + i * MA);
            const float2* Vj0 = (const float2*)(sV + j0 * MA);
            const float2* Vj1 = (const float2*)(sV + (j0 + 1) * MA);
            const float2* Cj0 = (const float2*)(Cc + j0 * MA);
            const float2* Cj1 = (const float2*)(Cc + (j0 + 1) * MA);
            float a0 = (i == j0) ? 0.01f : 0.f;
            float a1 = (i == j0 + 1) ? 0.01f : 0.f;
            #pragma unroll
            for (int k2 = 0; k2 < 16; k2++) {
                float2 z = Zr[k2], ci = Ci[k2];
                float2 v0 = Vj0[k2], v1 = Vj1[k2];
                float2 c0v = Cj0[k2], c1v = Cj1[k2];
                a0 += z.x * v0.x + z.y * v0.y + 0.01f * (ci.x * c0v.x + ci.y * c0v.y);
                a1 += z.x * v1.x + z.y * v1.y + 0.01f * (ci.x * c1v.x + ci.y * c1v.y);
            }
            *(float2*)(sS + i * 18 + j0) = make_float2(a0, a1);
        } else if (tid < 400) {
            const int i = tid - 384;
            const float2* Cr = (const float2*)(Cc + i * MA);
            float s = sy[cur][i];
            #pragma unroll
            for (int j = 0; j < 16; j++) {
                float2 cv = Cr[j];
                s -= cv.x * smup[2 * j] + cv.y * smup[2 * j + 1];
            }
            sd[i] = s;
        } else {
            float2* gp = (float2*)(g_Sigp + (bt << 10));
            for (int i2 = tid - 400; i2 < 512; i2 += 112) {
                int rr = i2 >> 4, c2 = i2 & 15;
                gp[i2] = *(const float2*)(sSigp + rr * MA + 2 * c2);
            }
        }
        __syncthreads();

        // ================= R3: warp0 solves S X = CSp | others prefetch t+1 =
        if (tid < 32) {
            const int c = tid;
            float Sc[P], Rc[P], piv[P];
            #pragma unroll
            for (int rr = 0; rr < P; rr++) {
                Sc[rr] = sS[rr * 18 + (c & 15)];
                Rc[rr] = sCSp[rr * MA + c];
            }
            #pragma unroll
            for (int j = 0; j < P; j++) {
                float f[P];
                #pragma unroll
                for (int rr = 0; rr < P; rr++) f[rr] = __shfl_sync(0xffffffffu, Sc[rr], j);
                float pinv = 1.0f / f[j];
                piv[j] = f[j];
                float sj = Sc[j] * pinv, rj = Rc[j] * pinv;
                #pragma unroll
                for (int rr = 0; rr < P; rr++) {
                    if (rr != j) { Sc[rr] -= f[rr] * sj; Rc[rr] -= f[rr] * rj; }
                }
            }
            #pragma unroll
            for (int rr = 0; rr < P; rr++) sX[rr * MA + c] = Rc[rr] / piv[rr];
        } else if (t + 1 < T) {
            const int pt = tid - 32;
            const size_t bt1 = bt + 1;
            const float2* An = (const float2*)(A + bt1 * (N * N));
            const float2* Cn = (const float2*)(C + bt1 * (P * N));
            const float2* Bn = (const float2*)(Bm + bt1 * (N * M));
            for (int i2 = pt; i2 < 512; i2 += 480) {
                int rr = i2 >> 4, c2 = i2 & 15;
                *(float2*)(sA[nxt] + rr * MA + 2 * c2) = An[i2];
            }
            if (pt < 256) {
                int rr = pt >> 4, c2 = pt & 15;
                *(float2*)(sC[nxt] + rr * MA + 2 * c2) = Cn[pt];
            }
            if (pt < 128) ((float2*)sB[nxt])[pt] = Bn[pt];
            if (pt < P) sy[nxt][pt] = Y[bt1 * P + pt];
            else if (pt < P + M) su[nxt][pt - P] = U[bt1 * M + (pt - P)];
        }
        __syncthreads();

        // ===== R4: Sf = Sigp - 0.5*(X^T CSp + CSp^T X) (2x2, fused sym) | mu_f
        if (tid < 256) {
            const int r0 = (tid >> 4) * 2, c0 = (tid & 15) * 2;
            float2 p0 = *(const float2*)(sSigp + r0 * MA + c0);
            float2 p1 = *(const float2*)(sSigp + (r0 + 1) * MA + c0);
            float m00 = 0, m01 = 0, m10 = 0, m11 = 0;
            #pragma unroll
            for (int j = 0; j < P; j++) {
                float2 xr = *(const float2*)(sX + j * MA + r0);
                float2 zr = *(const float2*)(sCSp + j * MA + r0);
                float2 xc = *(const float2*)(sX + j * MA + c0);
                float2 zc = *(const float2*)(sCSp + j * MA + c0);
                m00 += xr.x * zc.x + zr.x * xc.x;
                m01 += xr.x * zc.y + zr.x * xc.y;
                m10 += xr.y * zc.x + zr.y * xc.x;
                m11 += xr.y * zc.y + zr.y * xc.y;
            }
            float v00 = p0.x - 0.5f * m00, v01 = p0.y - 0.5f * m01;
            float v10 = p1.x - 0.5f * m10, v11 = p1.y - 0.5f * m11;
            *(float2*)(sSig + r0 * MA + c0) = make_float2(v00, v01);
            *(float2*)(sSig + (r0 + 1) * MA + c0) = make_float2(v10, v11);
            float* gf = g_Sigf + (bt << 10);
            *(float2*)(gf + r0 * 32 + c0) = make_float2(v00, v01);
            *(float2*)(gf + (r0 + 1) * 32 + c0) = make_float2(v10, v11);
        } else if (tid < 288) {
            const int i = tid - 256;
            float s = smup[i];
            #pragma unroll
            for (int j = 0; j < P; j++) s += sX[j * MA + i] * sd[j];
            smu[i] = s;
            g_muf[bt * N + i] = s;
        }
        __syncthreads();
    }
}

// =====================================================================
// Kernel 2: per (b,t) compute X_t = J_t^T, M_t, c_t. grid (127, 64), 128 thr.
// =====================================================================
__global__ __launch_bounds__(128) void k_J2(const float* __restrict__ A)
{
    const int t = blockIdx.x;      // 0..126
    const int b = blockIdx.y;
    const size_t bt = (size_t)b * T + t;
    const int tid = threadIdx.x;

    __shared__ __align__(16) float sA[N * MA], sSf[N * MA], sSp[N * MA];
    __shared__ __align__(16) float sG[N * MA], sXs[N * MA];
    __shared__ float smf[N], smp[N];

    {
        const float2* Ab = (const float2*)(A + bt * (N * N));
        const float2* gf = (const float2*)(g_Sigf + (bt << 10));
        const float2* gp = (const float2*)(g_Sigp + ((bt + 1) << 10));
        for (int i2 = tid; i2 < 512; i2 += 128) {
            int r = i2 >> 4, c = (i2 & 15) * 2;
            *(float2*)(sA + r * MA + c) = Ab[i2];
            *(float2*)(sSf + r * MA + c) = gf[i2];
            *(float2*)(sSp + r * MA + c) = gp[i2];
        }
        if (tid < N) {
            smf[tid] = g_muf[bt * N + tid];
            smp[tid] = g_mup[(bt + 1) * N + tid];
        }
    }
    __syncthreads();

    // G = A * Sf (2x2 tiles, 2 per thread)
    #pragma unroll
    for (int s = 0; s < 2; s++) {
        const int id = tid + s * 128;
        const int r0 = (id >> 4) * 2, c0 = (id & 15) * 2;
        const float2* Xr0 = (const float2*)(sA + r0 * MA);
        const float2* Xr1 = (const float2*)(sA + (r0 + 1) * MA);
        float a00 = 0, a01 = 0, a10 = 0, a11 = 0;
        #pragma unroll
        for (int k2 = 0; k2 < 16; k2++) {
            float2 x0 = Xr0[k2], x1 = Xr1[k2];
            float2 y0 = *(const float2*)(sSf + (2 * k2) * MA + c0);
            float2 y1 = *(const float2*)(sSf + (2 * k2 + 1) * MA + c0);
            a00 += x0.x * y0.x + x0.y * y1.x;  a01 += x0.x * y0.y + x0.y * y1.y;
            a10 += x1.x * y0.x + x1.y * y1.x;  a11 += x1.x * y0.y + x1.y * y1.y;
        }
        *(float2*)(sG + r0 * MA + c0) = make_float2(a00, a01);
        *(float2*)(sG + (r0 + 1) * MA + c0) = make_float2(a10, a11);
    }
    __syncthreads();

    // warp0: register GJ  Sp X = G
    if (tid < 32) {
        const int c = tid;
        float Sc[N], Gc[N];
        #pragma unroll
        for (int rr = 0; rr < N; rr++) {
            Sc[rr] = sSp[rr * MA + c];
            Gc[rr] = sG[rr * MA + c];
        }
        #pragma unroll
        for (int j = 0; j < N; j++) {
            float fj = __shfl_sync(0xffffffffu, Sc[j], j);
            float pinv = 1.0f / fj;
            Sc[j] *= pinv;
            Gc[j] *= pinv;
            float scj = Sc[j], gcj = Gc[j];
            #pragma unroll
            for (int rr = 0; rr < N; rr++) {
                if (rr != j) {
                    float f = __shfl_sync(0xffffffffu, Sc[rr], j);
                    Sc[rr] -= f * scj;
                    Gc[rr] -= f * gcj;
                }
            }
        }
        #pragma unroll
        for (int rr = 0; rr < N; rr++) sXs[rr * MA + c] = Gc[rr];
    }
    __syncthreads();

    const size_t jidx = (size_t)b * (T - 1) + t;

    if (tid < N) {
        float s = smf[tid];
        #pragma unroll
        for (int k = 0; k < N; k++) s -= sXs[k * MA + tid] * smp[k];
        g_c[jidx * N + tid] = s;
    }
    {
        float2* gj = (float2*)(g_J + jidx * (N * N));
        for (int i2 = tid; i2 < 512; i2 += 128) {
            int r = i2 >> 4, c = (i2 & 15) * 2;
            gj[i2] = *(const float2*)(sXs + r * MA + c);
        }
    }
    {
        float* gm = g_M + jidx * (N * N);
        #pragma unroll
        for (int s = 0; s < 2; s++) {
            const int id = tid + s * 128;
            const int r0 = (id >> 4) * 2, c0 = (id & 15) * 2;
            float2 f0 = *(const float2*)(sSf + r0 * MA + c0);
            float2 f1 = *(const float2*)(sSf + (r0 + 1) * MA + c0);
            float a00 = f0.x, a01 = f0.y, a10 = f1.x, a11 = f1.y;
            #pragma unroll
            for (int k = 0; k < N; k++) {
                float x0 = sXs[k * MA + r0], x1 = sXs[k * MA + r0 + 1];
                float2 g = *(const float2*)(sG + k * MA + c0);
                a00 -= x0 * g.x;  a01 -= x0 * g.y;
                a10 -= x1 * g.x;  a11 -= x1 * g.y;
            }
            *(float2*)(gm + r0 * 32 + c0) = make_float2(a00, a01);
            *(float2*)(gm + (r0 + 1) * 32 + c0) = make_float2(a10, a11);
        }
    }
}

// =====================================================================
// Kernel 3 (Phase A): compose chunk operators. grid (8, 64), 256 thr.
// =====================================================================
__global__ __launch_bounds__(256) void k_scanA()
{
    const int k = blockIdx.x, b = blockIdx.y;
    const int t_lo = CHS * k;
    const int t_hi = (k == NCH - 1) ? (T - 2) : (CHS * k + CHS - 1);
    const int tid = threadIdx.x;

    __shared__ __align__(16) float sXO[N * MA], sMO[N * MA];
    __shared__ __align__(16) float sXt[N * MA], sMt[N * MA];
    __shared__ __align__(16) float sW[N * MA], sXN[N * MA];
    __shared__ float scO[N], sct[N], scN[N];

    const int r0 = (tid >> 4) * 2, c0 = (tid & 15) * 2;

    {
        const size_t base = (size_t)b * (T - 1) + t_hi;
        const float2* gx = (const float2*)(g_J + base * (N * N));
        const float2* gm = (const float2*)(g_M + base * (N * N));
        for (int i2 = tid; i2 < 512; i2 += 256) {
            int r = i2 >> 4, c = (i2 & 15) * 2;
            *(float2*)(sXO + r * MA + c) = gx[i2];
            *(float2*)(sMO + r * MA + c) = gm[i2];
        }
        if (tid < N) scO[tid] = g_c[base * N + tid];
    }
    __syncthreads();

    for (int t = t_hi - 1; t >= t_lo; t--) {
        const size_t base = (size_t)b * (T - 1) + t;
        {
            const float2* gx = (const float2*)(g_J + base * (N * N));
            const float2* gm = (const float2*)(g_M + base * (N * N));
            for (int i2 = tid; i2 < 512; i2 += 256) {
                int r = i2 >> 4, c = (i2 & 15) * 2;
                *(float2*)(sXt + r * MA + c) = gx[i2];
                *(float2*)(sMt + r * MA + c) = gm[i2];
            }
            if (tid < N) sct[tid] = g_c[base * N + tid];
        }
        __syncthreads();

        {
            const float2* Mr0 = (const float2*)(sMO + r0 * MA);
            const float2* Mr1 = (const float2*)(sMO + (r0 + 1) * MA);
            const float2* Or0 = (const float2*)(sXO + r0 * MA);
            const float2* Or1 = (const float2*)(sXO + (r0 + 1) * MA);
            float w00 = 0, w01 = 0, w10 = 0, w11 = 0;
            float x00 = 0, x01 = 0, x10 = 0, x11 = 0;
            #pragma unroll
            for (int k2 = 0; k2 < 16; k2++) {
                float2 y0 = *(const float2*)(sXt + (2 * k2) * MA + c0);
                float2 y1 = *(const float2*)(sXt + (2 * k2 + 1) * MA + c0);
                float2 m0 = Mr0[k2], m1 = Mr1[k2];
                float2 o0 = Or0[k2], o1 = Or1[k2];
                w00 += m0.x * y0.x + m0.y * y1.x;  w01 += m0.x * y0.y + m0.y * y1.y;
                w10 += m1.x * y0.x + m1.y * y1.x;  w11 += m1.x * y0.y + m1.y * y1.y;
                x00 += o0.x * y0.x + o0.y * y1.x;  x01 += o0.x * y0.y + o0.y * y1.y;
                x10 += o1.x * y0.x + o1.y * y1.x;  x11 += o1.x * y0.y + o1.y * y1.y;
            }
            *(float2*)(sW + r0 * MA + c0) = make_float2(w00, w01);
            *(float2*)(sW + (r0 + 1) * MA + c0) = make_float2(w10, w11);
            *(float2*)(sXN + r0 * MA + c0) = make_float2(x00, x01);
            *(float2*)(sXN + (r0 + 1) * MA + c0) = make_float2(x10, x11);
        }
        if (tid < N) {
            float s = sct[tid];
            #pragma unroll
            for (int j = 0; j < N; j++) s += sXt[j * MA + tid] * scO[j];
            scN[tid] = s;
        }
        __syncthreads();

        {
            float2 f0 = *(const float2*)(sMt + r0 * MA + c0);
            float2 f1 = *(const float2*)(sMt + (r0 + 1) * MA + c0);
            float a00 = f0.x, a01 = f0.y, a10 = f1.x, a11 = f1.y;
            #pragma unroll
            for (int j = 0; j < N; j++) {
                float2 xj = *(const float2*)(sXt + j * MA + r0);
                float2 wj = *(const float2*)(sW + j * MA + c0);
                a00 += xj.x * wj.x;  a01 += xj.x * wj.y;
                a10 += xj.y * wj.x;  a11 += xj.y * wj.y;
            }
            *(float2*)(sMO + r0 * MA + c0) = make_float2(a00, a01);
            *(float2*)(sMO + (r0 + 1) * MA + c0) = make_float2(a10, a11);
            *(float2*)(sXO + r0 * MA + c0) = *(const float2*)(sXN + r0 * MA + c0);
            *(float2*)(sXO + (r0 + 1) * MA + c0) = *(const float2*)(sXN + (r0 + 1) * MA + c0);
        }
        if (tid < N) scO[tid] = scN[tid];
        __syncthreads();
    }

    {
        const size_t obase = (size_t)b * NCH + k;
        float2* gx = (float2*)(g_OX + obase * (N * N));
        float2* gm = (float2*)(g_OM + obase * (N * N));
        for (int i2 = tid; i2 < 512; i2 += 256) {
            int r = i2 >> 4, c = (i2 & 15) * 2;
            gx[i2] = *(const float2*)(sXO + r * MA + c);
            gm[i2] = *(const float2*)(sMO + r * MA + c);
        }
        if (tid < N) g_Oc[obase * N + tid] = scO[tid];
    }
}

// =====================================================================
// Kernel 4 (Phase B): boundary states per batch. grid 64, 256 thr.
// =====================================================================
__global__ __launch_bounds__(256) void k_scanB(float* __restrict__ out)
{
    const int b = blockIdx.x;
    const int tid = threadIdx.x;

    __shared__ __align__(16) float sS[N * MA], sX[N * MA], sMm[N * MA], sW[N * MA];
    __shared__ float smu[N], smuN[N], sc[N];

    const int r0 = (tid >> 4) * 2, c0 = (tid & 15) * 2;

    {
        const size_t btL = (size_t)b * T + (T - 1);
        const float2* gf = (const float2*)(g_Sigf + (btL << 10));
        float2* ge = (float2*)(g_eS + ((size_t)b * NCH + (NCH - 1)) * (N * N));
        for (int i2 = tid; i2 < 512; i2 += 256) {
            int r = i2 >> 4, c = (i2 & 15) * 2;
            float2 v = gf[i2];
            *(float2*)(sS + r * MA + c) = v;
            ge[i2] = v;
            float* o = out + (btL * N + r) * (N + 1) + 1 + c;
            o[0] = v.x; o[1] = v.y;
        }
        if (tid < N) {
            float v = g_muf[btL * N + tid];
            smu[tid] = v;
            g_emu[((size_t)b * NCH + (NCH - 1)) * N + tid] = v;
            out[(btL * N + tid) * (N + 1)] = v;
        }
    }
    __syncthreads();

    for (int k = NCH - 2; k >= 0; k--) {
        const size_t obase = (size_t)b * NCH + (k + 1);
        {
            const float2* gx = (const float2*)(g_OX + obase * (N * N));
            const float2* gm = (const float2*)(g_OM + obase * (N * N));
            for (int i2 = tid; i2 < 512; i2 += 256) {
                int r = i2 >> 4, c = (i2 & 15) * 2;
                *(float2*)(sX + r * MA + c) = gx[i2];
                *(float2*)(sMm + r * MA + c) = gm[i2];
            }
            if (tid < N) sc[tid] = g_Oc[obase * N + tid];
        }
        __syncthreads();

        {
            const float2* Sr0 = (const float2*)(sS + r0 * MA);
            const float2* Sr1 = (const float2*)(sS + (r0 + 1) * MA);
            float a00 = 0, a01 = 0, a10 = 0, a11 = 0;
            #pragma unroll
            for (int k2 = 0; k2 < 16; k2++) {
                float2 x0 = Sr0[k2], x1 = Sr1[k2];
                float2 y0 = *(const float2*)(sX + (2 * k2) * MA + c0);
                float2 y1 = *(const float2*)(sX + (2 * k2 + 1) * MA + c0);
                a00 += x0.x * y0.x + x0.y * y1.x;  a01 += x0.x * y0.y + x0.y * y1.y;
                a10 += x1.x * y0.x + x1.y * y1.x;  a11 += x1.x * y0.y + x1.y * y1.y;
            }
            *(float2*)(sW + r0 * MA + c0) = make_float2(a00, a01);
            *(float2*)(sW + (r0 + 1) * MA + c0) = make_float2(a10, a11);
        }
        if (tid < N) {
            float s = sc[tid];
            #pragma unroll
            for (int j = 0; j < N; j++) s += sX[j * MA + tid] * smu[j];
            smuN[tid] = s;
        }
        __syncthreads();

        {
            float2 f0 = *(const float2*)(sMm + r0 * MA + c0);
            float2 f1 = *(const float2*)(sMm + (r0 + 1) * MA + c0);
            float a00 = f0.x, a01 = f0.y, a10 = f1.x, a11 = f1.y;
            #pragma unroll
            for (int j = 0; j < N; j++) {
                float2 xj = *(const float2*)(sX + j * MA + r0);
                float2 wj = *(const float2*)(sW + j * MA + c0);
                a00 += xj.x * wj.x;  a01 += xj.x * wj.y;
                a10 += xj.y * wj.x;  a11 += xj.y * wj.y;
            }
            *(float2*)(sS + r0 * MA + c0) = make_float2(a00, a01);
            *(float2*)(sS + (r0 + 1) * MA + c0) = make_float2(a10, a11);
            float* ge = g_eS + ((size_t)b * NCH + k) * (N * N);
            *(float2*)(ge + r0 * 32 + c0) = make_float2(a00, a01);
            *(float2*)(ge + (r0 + 1) * 32 + c0) = make_float2(a10, a11);
        }
        if (tid < N) {
            smu[tid] = smuN[tid];
            g_emu[((size_t)b * NCH + k) * N + tid] = smuN[tid];
        }
        __syncthreads();
    }
}

// =====================================================================
// Kernel 5 (Phase C): per-chunk backward recursion. grid (8, 64), 256 thr.
// =====================================================================
__global__ __launch_bounds__(256) void k_scanC(float* __restrict__ out)
{
    const int k = blockIdx.x, b = blockIdx.y;
    const int t_lo = CHS * k;
    const int t_hi = (k == NCH - 1) ? (T - 2) : (CHS * k + CHS - 1);
    const int tid = threadIdx.x;

    __shared__ __align__(16) float sS[N * MA], sX[N * MA], sMm[N * MA], sW[N * MA];
    __shared__ float smu[N], smuN[N], sc[N];

    const int r0 = (tid >> 4) * 2, c0 = (tid & 15) * 2;

    {
        const size_t ebase = (size_t)b * NCH + k;
        const float2* ge = (const float2*)(g_eS + ebase * (N * N));
        for (int i2 = tid; i2 < 512; i2 += 256) {
            int r = i2 >> 4, c = (i2 & 15) * 2;
            *(float2*)(sS + r * MA + c) = ge[i2];
        }
        if (tid < N) smu[tid] = g_emu[ebase * N + tid];
    }
    __syncthreads();

    for (int t = t_hi; t >= t_lo; t--) {
        const size_t base = (size_t)b * (T - 1) + t;
        const size_t bt = (size_t)b * T + t;
        {
            const float2* gx = (const float2*)(g_J + base * (N * N));
            const float2* gm = (const float2*)(g_M + base * (N * N));
            for (int i2 = tid; i2 < 512; i2 += 256) {
                int r = i2 >> 4, c = (i2 & 15) * 2;
                *(float2*)(sX + r * MA + c) = gx[i2];
                *(float2*)(sMm + r * MA + c) = gm[i2];
            }
            if (tid < N) sc[tid] = g_c[base * N + tid];
        }
        __syncthreads();

        {
            const float2* Sr0 = (const float2*)(sS + r0 * MA);
            const float2* Sr1 = (const float2*)(sS + (r0 + 1) * MA);
            float a00 = 0, a01 = 0, a10 = 0, a11 = 0;
            #pragma unroll
            for (int k2 = 0; k2 < 16; k2++) {
                float2 x0 = Sr0[k2], x1 = Sr1[k2];
                float2 y0 = *(const float2*)(sX + (2 * k2) * MA + c0);
                float2 y1 = *(const float2*)(sX + (2 * k2 + 1) * MA + c0);
                a00 += x0.x * y0.x + x0.y * y1.x;  a01 += x0.x * y0.y + x0.y * y1.y;
                a10 += x1.x * y0.x + x1.y * y1.x;  a11 += x1.x * y0.y + x1.y * y1.y;
            }
            *(float2*)(sW + r0 * MA + c0) = make_float2(a00, a01);
            *(float2*)(sW + (r0 + 1) * MA + c0) = make_float2(a10, a11);
        }
        if (tid < N) {
            float s = sc[tid];
            #pragma unroll
            for (int j = 0; j < N; j++) s += sX[j * MA + tid] * smu[j];
            smuN[tid] = s;
        }
        __syncthreads();

        {
            float2 f0 = *(const float2*)(sMm + r0 * MA + c0);
            float2 f1 = *(const float2*)(sMm + (r0 + 1) * MA + c0);
            float a00 = f0.x, a01 = f0.y, a10 = f1.x, a11 = f1.y;
            #pragma unroll
            for (int j = 0; j < N; j++) {
                float2 xj = *(const float2*)(sX + j * MA + r0);
                float2 wj = *(const float2*)(sW + j * MA + c0);
                a00 += xj.x * wj.x;  a01 += xj.x * wj.y;
                a10 += xj.y * wj.x;  a11 += xj.y * wj.y;
            }
            *(float2*)(sS + r0 * MA + c0) = make_float2(a00, a01);
            *(float2*)(sS + (r0 + 1) * MA + c0) = make_float2(a10, a11);
            float* o = out + (bt * N + r0) * (N + 1) + 1 + c0;
            o[0] = a00; o[1] = a01;
            o[N + 1] = a10; o[N + 2] = a11;
        }
        if (tid < N) {
            smu[tid] = smuN[tid];
            out[(bt * N + tid) * (N + 1)] = smuN[tid];
        }
        __syncthreads();
    }
}

extern "C" void kernel_launch(void* const* d_in, const int* in_sizes, int n_in,
                              void* d_out, int out_size) {
    (void)in_sizes; (void)n_in; (void)out_size;
    const float* Y   = (const float*)d_in[0];
    const float* U   = (const float*)d_in[1];
    const float* A   = (const float*)d_in[2];
    const float* Bm  = (const float*)d_in[3];
    const float* C   = (const float*)d_in[4];
    const float* mu0 = (const float*)d_in[5];
    const float* S0  = (const float*)d_in[6];
    float* out = (float*)d_out;

    k_fwd<<<BATCH, NTF>>>(Y, U, A, Bm, C, mu0, S0);
    k_J2<<<dim3(T - 1, BATCH), 128>>>(A);
    k_scanA<<<dim3(NCH, BATCH), 256>>>();
    k_scanB<<<BATCH, 256>>>(out);
    k_scanC<<<dim3(NCH, BATCH), 256>>>(out);
}